// round 13
// baseline (speedup 1.0000x reference)
#include <cuda_runtime.h>
#include <math.h>

// Problem constants
constexpr int B_  = 256;
constexpr int N_  = 2048;
constexpr int M_  = 64;
constexpr int C_  = 512;
constexpr int PR_ = 70;   // M + 3 + SHIFT
constexpr int PW_ = 198;  // PR + 2M
constexpr float EPSF = 1e-8f;

// Output layout (floats): ntm_out, memory, read_out, new_read_w, new_write_w
constexpr size_t OUT_MEM = 65536;
constexpr size_t OUT_RO  = 33619968;
constexpr size_t OUT_RW  = 33685504;
constexpr size_t OUT_WW  = 35782656;

// ---------------- device scratch ----------------
__device__ float g_ctrl[B_*C_];
__device__ float g_rp  [4*B_*PR_];
__device__ float g_wp  [4*B_*PW_];
__device__ float g_dot [5*(size_t)B_*N_];
__device__ float g_norm[(size_t)B_*N_];
__device__ float g_base[6*(size_t)B_*N_];   // base dots: Da,Db,S1,S2,T0,T1
__device__ float g_ropart[8*B_*256];

__device__ __forceinline__ float softplusf(float x){ return x > 20.f ? x : log1pf(expf(x)); }
__device__ __forceinline__ float sigmoidf (float x){ return 1.f/(1.f+expf(-x)); }

// ---------------- GEMM body (proven): tile 32x64, K-step 32, 256 threads ----------------
__device__ __forceinline__ void gemm_body(
    const float* __restrict__ A0, int ca,
    const float* __restrict__ A1, int cb,
    const float* __restrict__ W, const float* __restrict__ bias,
    float* __restrict__ out, int Nc)
{
    int col0 = blockIdx.x * 64;
    if (col0 >= Nc) return;
    int row0 = blockIdx.y * 32;
    int K = ca + cb;

    __shared__ float As[32][33];
    __shared__ float Ws[32][64];
    int tid = threadIdx.x;
    int tx = tid & 15, ty = tid >> 4;
    float acc[2][4] = {};

    for (int k0 = 0; k0 < K; k0 += 32) {
        {
            int m  = tid >> 3;
            int kk = (tid & 7) * 4;
            int r = row0 + m, c = k0 + kk;
            float4 v;
            if (c < ca) v = *(const float4*)(A0 + (size_t)r*ca + c);
            else        v = *(const float4*)(A1 + (size_t)r*cb + (c - ca));
            As[m][kk] = v.x; As[m][kk+1] = v.y; As[m][kk+2] = v.z; As[m][kk+3] = v.w;
        }
        {
            int kk = tid >> 3;
            int n0 = (tid & 7) * 8;
            const float* wrow = W + (size_t)(k0 + kk)*Nc + col0 + n0;
            #pragma unroll
            for (int j = 0; j < 8; j++) {
                int gn = col0 + n0 + j;
                Ws[kk][n0 + j] = (gn < Nc) ? wrow[j] : 0.f;
            }
        }
        __syncthreads();
        #pragma unroll
        for (int kk = 0; kk < 32; kk++) {
            float a0 = As[ty*2 + 0][kk];
            float a1 = As[ty*2 + 1][kk];
            float4 w4 = *(const float4*)&Ws[kk][tx*4];
            acc[0][0] += a0*w4.x; acc[0][1] += a0*w4.y; acc[0][2] += a0*w4.z; acc[0][3] += a0*w4.w;
            acc[1][0] += a1*w4.x; acc[1][1] += a1*w4.y; acc[1][2] += a1*w4.z; acc[1][3] += a1*w4.w;
        }
        __syncthreads();
    }
    #pragma unroll
    for (int i = 0; i < 2; i++) {
        int gm = row0 + ty*2 + i;
        #pragma unroll
        for (int j = 0; j < 4; j++) {
            int gn = col0 + tx*4 + j;
            if (gn < Nc) out[(size_t)gm*Nc + gn] = acc[i][j] + bias[gn];
        }
    }
}

__global__ void gemm_cat_kernel(const float* __restrict__ A0, int ca,
                                const float* __restrict__ A1, int cb,
                                const float* __restrict__ W, const float* __restrict__ bias,
                                float* __restrict__ out, int Nc)
{
    gemm_body(A0, ca, A1, cb, W, bias, out, Nc);
}

__global__ void gemm_heads_kernel(const float* __restrict__ ctrl,
                                  const float* __restrict__ readW, const float* __restrict__ readb,
                                  float* __restrict__ rp,
                                  const float* __restrict__ writeW, const float* __restrict__ writeb,
                                  float* __restrict__ wp)
{
    int h = blockIdx.z;
    const float *W, *bias; float* out; int Nc;
    if (h < 4) {
        W = readW + (size_t)h*C_*PR_; bias = readb + h*PR_;
        out = rp + (size_t)h*B_*PR_;  Nc = PR_;
    } else {
        int g = h - 4;
        W = writeW + (size_t)g*C_*PW_; bias = writeb + g*PW_;
        out = wp + (size_t)g*B_*PW_;   Nc = PW_;
    }
    gemm_body(ctrl, C_, nullptr, 0, W, bias, out, Nc);
}

// ---------------- Pass A: thread-per-row, smem constants, zero shuffles ----------------
__global__ void __launch_bounds__(256) passA_kernel(const float* __restrict__ mem)
{
    int bc = blockIdx.x; int b = bc >> 3; int nb = (bc & 7) << 8;
    int tid = threadIdx.x;

    __shared__ float cst[11][64];
    for (int i = tid; i < 5*64; i += 256) {
        int h = i >> 6, m = i & 63;
        cst[h][m] = (h < 4) ? g_rp[((size_t)h*B_ + b)*PR_ + m]
                            : g_wp[(size_t)b*PW_ + m];
    }
    if (tid < 64) {
        const float* wp0 = g_wp + (size_t)b*PW_;
        const float* wp1 = g_wp + ((size_t)B_ + b)*PW_;
        float e0 = sigmoidf(wp0[70 + tid]);
        float a0 = tanhf(wp0[134 + tid]);
        float k1 = wp1[tid];
        cst[5][tid]  = k1;
        cst[6][tid]  = e0*k1;
        cst[7][tid]  = e0;
        cst[8][tid]  = e0*e0;
        cst[9][tid]  = a0;
        cst[10][tid] = e0*a0;
    }
    __syncthreads();

    size_t ix = (size_t)b*N_ + nb + tid;
    const float4* rp4 = (const float4*)(mem + ix*M_);

    float acc[12] = {};
    #pragma unroll
    for (int mb = 0; mb < 16; mb++) {
        float4 d = rp4[mb];
        float4 c[11];
        #pragma unroll
        for (int ci = 0; ci < 11; ci++)
            c[ci] = *(const float4*)&cst[ci][mb*4];
        float vv[4] = {d.x, d.y, d.z, d.w};
        #pragma unroll
        for (int j = 0; j < 4; j++) {
            float v  = vv[j];
            float vs = v*v;
            acc[0]  += vs;
            acc[1]  += v * ((const float*)&c[0])[j];
            acc[2]  += v * ((const float*)&c[1])[j];
            acc[3]  += v * ((const float*)&c[2])[j];
            acc[4]  += v * ((const float*)&c[3])[j];
            acc[5]  += v * ((const float*)&c[4])[j];
            acc[6]  += v * ((const float*)&c[5])[j];
            acc[7]  += v * ((const float*)&c[6])[j];
            acc[8]  += vs * ((const float*)&c[7])[j];
            acc[9]  += vs * ((const float*)&c[8])[j];
            acc[10] += v * ((const float*)&c[9])[j];
            acc[11] += v * ((const float*)&c[10])[j];
        }
    }

    const size_t P = (size_t)B_*N_;
    g_norm[ix] = sqrtf(acc[0]);
    #pragma unroll
    for (int h = 0; h < 5; h++) g_dot[(size_t)h*P + ix] = acc[1+h];
    #pragma unroll
    for (int r = 0; r < 6; r++) g_base[(size_t)r*P + ix] = acc[6+r];
}

// ---------------- block reduction helpers (512 threads) ----------------
__device__ __forceinline__ float block_reduce_sum512(float v, float* sbuf)
{
    int tid = threadIdx.x;
    #pragma unroll
    for (int o = 16; o > 0; o >>= 1) v += __shfl_xor_sync(0xffffffffu, v, o);
    if ((tid & 31) == 0) sbuf[tid >> 5] = v;
    __syncthreads();
    if (tid < 32) {
        float x = (tid < 16) ? sbuf[tid] : 0.f;
        #pragma unroll
        for (int o = 8; o > 0; o >>= 1) x += __shfl_xor_sync(0xffffffffu, x, o);
        if (tid == 0) sbuf[0] = x;
    }
    __syncthreads();
    float r = sbuf[0];
    __syncthreads();
    return r;
}

__device__ __forceinline__ float block_reduce_max512(float v, float* sbuf)
{
    int tid = threadIdx.x;
    #pragma unroll
    for (int o = 16; o > 0; o >>= 1) v = fmaxf(v, __shfl_xor_sync(0xffffffffu, v, o));
    if ((tid & 31) == 0) sbuf[tid >> 5] = v;
    __syncthreads();
    if (tid < 32) {
        float x = (tid < 16) ? sbuf[tid] : -3.4e38f;
        #pragma unroll
        for (int o = 8; o > 0; o >>= 1) x = fmaxf(x, __shfl_xor_sync(0xffffffffu, x, o));
        if (tid == 0) sbuf[0] = x;
    }
    __syncthreads();
    float r = sbuf[0];
    __syncthreads();
    return r;
}

// ---------------- addressing tail (512 threads, 4 items/thread) ----------------
__device__ __forceinline__ void address_tail(
    float* x, float g, float s0, float s1, float s2, float gamma,
    const float* __restrict__ wpb, float* __restrict__ woutb,
    float* wg, float* rbuf)
{
    int tid = threadIdx.x;
    float mx = fmaxf(fmaxf(x[0], x[1]), fmaxf(x[2], x[3]));
    float bmax = block_reduce_max512(mx, rbuf);
    float lsum = 0.f;
    #pragma unroll
    for (int i = 0; i < 4; i++) {
        float e = __expf(x[i] - bmax);
        wg[tid + i*512] = e;
        lsum += e;
    }
    float bsum = block_reduce_sum512(lsum, rbuf);
    float inv = 1.f / bsum;
    #pragma unroll
    for (int i = 0; i < 4; i++) {
        int n = tid + i*512;
        wg[n] = g * (wg[n]*inv) + (1.f-g) * wpb[n];
    }
    __syncthreads();
    float wpow[4];
    lsum = 0.f;
    #pragma unroll
    for (int i = 0; i < 4; i++) {
        int n = tid + i*512;
        float ws = s0*wg[(n+1)&(N_-1)] + s1*wg[n] + s2*wg[(n-1)&(N_-1)];
        float t = __powf(ws + EPSF, gamma);
        wpow[i] = t;
        lsum += t;
    }
    float psum = block_reduce_sum512(lsum, rbuf);
    float ip = 1.f / psum;
    #pragma unroll
    for (int i = 0; i < 4; i++) {
        float wv = wpow[i]*ip;
        woutb[tid + i*512] = wv;
        x[i] = wv;
    }
}

__device__ __forceinline__ void head_scalars(const float* __restrict__ p, float ksum, float* sc)
{
    sc[0] = sqrtf(ksum);
    sc[1] = softplusf(p[64]);
    sc[2] = sigmoidf(p[65]);
    float a0 = p[66], a1 = p[67], a2 = p[68];
    float mx = fmaxf(a0, fmaxf(a1, a2));
    float e0 = expf(a0-mx), e1 = expf(a1-mx), e2 = expf(a2-mx);
    float es = e0 + e1 + e2;
    sc[3] = e0/es; sc[4] = e1/es; sc[5] = e2/es;
    sc[6] = 1.f + softplusf(p[69]);
}

__device__ __forceinline__ void poly_x(
    float* x, const float* wdone, size_t base,
    float CC, float UU, float knorm, float beta)
{
    int tid = threadIdx.x;
    const size_t P = (size_t)B_*N_;
    const float* nrmp = g_norm + base;
    #pragma unroll
    for (int i = 0; i < 4; i++) {
        int n = tid + i*512;
        float w  = wdone[i];
        float Da = g_base[0*P + base + n];
        float Db = g_base[1*P + base + n];
        float S1 = g_base[2*P + base + n];
        float S2 = g_base[3*P + base + n];
        float T0 = g_base[4*P + base + n];
        float T1 = g_base[5*P + base + n];
        float nr = nrmp[n];
        float S0 = nr*nr;
        float dotv = Da - w*Db + w*CC;
        float w2 = w*w;
        float nsq = S0 - 2.f*w*S1 + w2*S2 + 2.f*w*T0 - 2.f*w2*T1 + w2*UU;
        float nn = sqrtf(fmaxf(nsq, 0.f));
        x[i] = beta * (dotv / (nn*knorm + EPSF));
    }
}

// ---------------- fused addressing: 4 read heads (y=0..3) + write heads 0&1 (y=4) -------------
__global__ void __launch_bounds__(512) address5_kernel(
    const float* __restrict__ prw,
    const float* __restrict__ pww,
    float* __restrict__ o_rw,
    float* __restrict__ o_ww)
{
    __shared__ float wg[2048];
    __shared__ float rbuf[32];
    __shared__ float sc[16];
    int b = blockIdx.x, h = blockIdx.y, tid = threadIdx.x;
    size_t base = (size_t)b*N_;
    const size_t P = (size_t)B_*N_;

    if (h < 4) {
        const float* p = g_rp + ((size_t)h*B_ + b)*PR_;
        float kv = 0.f;
        if (tid < 64) { float xx = p[tid]; kv = xx*xx; }
        float ksum = block_reduce_sum512(kv, rbuf);
        if (tid == 0) head_scalars(p, ksum, sc);
        __syncthreads();
        float knorm = sc[0], beta = sc[1], g = sc[2];
        float s0 = sc[3], s1 = sc[4], s2 = sc[5], gamma = sc[6];

        const float* dotb = g_dot + (size_t)h*P + base;
        const float* nrmb = g_norm + base;
        float x[4];
        #pragma unroll
        for (int i = 0; i < 4; i++) {
            int n = tid + i*512;
            x[i] = beta * (dotb[n] / (nrmb[n]*knorm + EPSF));
        }
        address_tail(x, g, s0, s1, s2, gamma,
                     prw + (size_t)h*P + base, o_rw + (size_t)h*P + base, wg, rbuf);
    } else {
        const float* p0 = g_wp + (size_t)b*PW_;
        const float* p1 = g_wp + ((size_t)1*B_ + b)*PW_;
        float kv0 = 0.f, kv1 = 0.f, c1 = 0.f, c2 = 0.f;
        if (tid < 64) {
            float k0 = p0[tid], k1 = p1[tid];
            float a0 = tanhf(p0[134 + tid]);
            kv0 = k0*k0; kv1 = k1*k1; c1 = a0*k1; c2 = a0*a0;
        }
        float ks0 = block_reduce_sum512(kv0, rbuf);
        float ks1 = block_reduce_sum512(kv1, rbuf);
        float Cc  = block_reduce_sum512(c1, rbuf);
        float U   = block_reduce_sum512(c2, rbuf);
        if (tid == 0) {
            head_scalars(p0, ks0, sc);
            head_scalars(p1, ks1, sc + 7);
            sc[14] = Cc; sc[15] = U;
        }
        __syncthreads();

        float knorm = sc[0], beta = sc[1], g = sc[2];
        float s0 = sc[3], s1 = sc[4], s2 = sc[5], gamma = sc[6];
        const float* dotb = g_dot + 4*P + base;
        const float* nrmb = g_norm + base;
        float x[4];
        #pragma unroll
        for (int i = 0; i < 4; i++) {
            int n = tid + i*512;
            x[i] = beta * (dotb[n] / (nrmb[n]*knorm + EPSF));
        }
        address_tail(x, g, s0, s1, s2, gamma, pww + base, o_ww + base, wg, rbuf);
        __syncthreads();
        float y[4];
        poly_x(y, x, base, sc[14], sc[15], sc[7], sc[8]);
        address_tail(y, sc[9], sc[10], sc[11], sc[12], sc[13],
                     pww + P + base, o_ww + P + base, wg, rbuf);
    }
}

// ---------------- fused write heads 2 & 3 ----------------
__global__ void __launch_bounds__(512) addr23_kernel(
    const float* __restrict__ pww,
    float* __restrict__ o_ww)
{
    __shared__ float wg[2048];
    __shared__ float rbuf[32];
    __shared__ float sc[16];
    int b = blockIdx.x, tid = threadIdx.x;
    size_t base = (size_t)b*N_;
    const size_t P = (size_t)B_*N_;

    const float* p2 = g_wp + ((size_t)2*B_ + b)*PW_;
    const float* p3 = g_wp + ((size_t)3*B_ + b)*PW_;
    float kv2 = 0.f, kv3 = 0.f, c1 = 0.f, c2 = 0.f;
    if (tid < 64) {
        float k2 = p2[tid], k3 = p3[tid];
        float a2 = tanhf(p2[134 + tid]);
        kv2 = k2*k2; kv3 = k3*k3; c1 = a2*k3; c2 = a2*a2;
    }
    float ks2 = block_reduce_sum512(kv2, rbuf);
    float ks3 = block_reduce_sum512(kv3, rbuf);
    float Cc  = block_reduce_sum512(c1, rbuf);
    float U   = block_reduce_sum512(c2, rbuf);
    if (tid == 0) {
        head_scalars(p2, ks2, sc);
        head_scalars(p3, ks3, sc + 7);
        sc[14] = Cc; sc[15] = U;
    }
    __syncthreads();

    float knorm = sc[0], beta = sc[1], g = sc[2];
    float s0 = sc[3], s1 = sc[4], s2 = sc[5], gamma = sc[6];
    const float* dotb = g_dot + 4*P + base;
    const float* nrmb = g_norm + base;
    float x[4];
    #pragma unroll
    for (int i = 0; i < 4; i++) {
        int n = tid + i*512;
        x[i] = beta * (dotb[n] / (nrmb[n]*knorm + EPSF));
    }
    address_tail(x, g, s0, s1, s2, gamma, pww + 2*P + base, o_ww + 2*P + base, wg, rbuf);
    __syncthreads();
    float y[4];
    poly_x(y, x, base, sc[14], sc[15], sc[7], sc[8]);
    address_tail(y, sc[9], sc[10], sc[11], sc[12], sc[13],
                 pww + 3*P + base, o_ww + 3*P + base, wg, rbuf);
}

// ---------------- Sweep 1 (two-phase thread-per-row): stats + reads einsum ----------------
__global__ void __launch_bounds__(256) sweep1_kernel(
    const float* __restrict__ mem_in,
    const float* __restrict__ wr,
    const float* __restrict__ wwp,
    float* __restrict__ ro_part)
{
    int bc = blockIdx.x; int b = bc >> 3; int nb = (bc & 7) << 8;
    int tid = threadIdx.x, wid = tid >> 5, lane = tid & 31;
    const size_t P = (size_t)B_*N_;

    __shared__ float cst[11][64];
    __shared__ float ws4[256][4];
    __shared__ float2 sred[8][4][32];
    if (tid < 64) {
        const float* p0 = g_wp + (size_t)b*PW_;
        const float* p1 = g_wp + ((size_t)1*B_ + b)*PW_;
        const float* p2 = g_wp + ((size_t)2*B_ + b)*PW_;
        const float* p3 = g_wp + ((size_t)3*B_ + b)*PW_;
        float e2 = sigmoidf(p2[70 + tid]);
        float a2 = tanhf(p2[134 + tid]);
        float k3 = p3[tid];
        cst[0][tid]  = p2[tid];
        cst[1][tid]  = e2*k3;
        cst[2][tid]  = e2;
        cst[3][tid]  = e2*e2;
        cst[4][tid]  = a2;
        cst[5][tid]  = e2*a2;
        cst[6][tid]  = k3;
        cst[7][tid]  = sigmoidf(p0[70 + tid]);
        cst[8][tid]  = tanhf(p0[134 + tid]);
        cst[9][tid]  = sigmoidf(p1[70 + tid]);
        cst[10][tid] = tanhf(p1[134 + tid]);
    }
    size_t ix = (size_t)b*N_ + nb + tid;
    #pragma unroll
    for (int h = 0; h < 4; h++) ws4[tid][h] = wr[(size_t)h*P + ix];
    __syncthreads();

    // phase 1: per-row stats
    float w0 = wwp[ix], w1 = wwp[P + ix];
    const float4* rp4 = (const float4*)(mem_in + ix*M_);
    float acc[8] = {};
    #pragma unroll
    for (int mb = 0; mb < 16; mb++) {
        float4 d = rp4[mb];
        float4 c[11];
        #pragma unroll
        for (int ci = 0; ci < 11; ci++)
            c[ci] = *(const float4*)&cst[ci][mb*4];
        float vv[4] = {d.x, d.y, d.z, d.w};
        #pragma unroll
        for (int j = 0; j < 4; j++) {
            float v  = vv[j];
            float e0 = ((const float*)&c[7])[j], a0 = ((const float*)&c[8])[j];
            float e1 = ((const float*)&c[9])[j], a1 = ((const float*)&c[10])[j];
            float m1 = v*(1.f - w0*e0) + w0*a0;
            float m2 = m1*(1.f - w1*e1) + w1*a1;
            float s  = m2*m2;
            acc[0] += m2 * ((const float*)&c[0])[j];
            acc[1] += s;
            acc[2] += m2 * ((const float*)&c[6])[j];
            acc[3] += m2 * ((const float*)&c[1])[j];
            acc[4] += s  * ((const float*)&c[2])[j];
            acc[5] += s  * ((const float*)&c[3])[j];
            acc[6] += m2 * ((const float*)&c[4])[j];
            acc[7] += m2 * ((const float*)&c[5])[j];
        }
    }
    g_dot[4*P + ix] = acc[0];
    g_norm[ix] = sqrtf(acc[1]);
    #pragma unroll
    for (int r = 0; r < 6; r++) g_base[(size_t)r*P + ix] = acc[2+r];

    // phase 2: reads einsum (lane-per-m, L2-hot re-read)
    float2 racc[4] = {{0,0},{0,0},{0,0},{0,0}};
    size_t rowbase = (size_t)b*N_ + nb + wid*32;
    #pragma unroll 4
    for (int r = 0; r < 32; r++) {
        float2 v2 = *(const float2*)(mem_in + (rowbase + r)*M_ + 2*lane);
        float4 w4 = *(const float4*)&ws4[wid*32 + r][0];
        racc[0].x += w4.x*v2.x; racc[0].y += w4.x*v2.y;
        racc[1].x += w4.y*v2.x; racc[1].y += w4.y*v2.y;
        racc[2].x += w4.z*v2.x; racc[2].y += w4.z*v2.y;
        racc[3].x += w4.w*v2.x; racc[3].y += w4.w*v2.y;
    }
    #pragma unroll
    for (int h = 0; h < 4; h++) sred[wid][h][lane] = racc[h];
    __syncthreads();
    int h = tid >> 6, m = tid & 63;
    int l = m >> 1, c = m & 1;
    float s = 0.f;
    #pragma unroll
    for (int w = 0; w < 8; w++) {
        float2 t = sred[w][h][l];
        s += c ? t.y : t.x;
    }
    ro_part[(size_t)(bc & 7)*B_*256 + (size_t)b*256 + h*64 + m] = s;
}

// ---------------- Fused tail: sweep2 thread-per-row (blocks 0..2047) + out GEMM (2048..2079) --
__global__ void __launch_bounds__(256) tail_kernel(
    const float* __restrict__ mem_in, float* __restrict__ mem_out,
    const float* __restrict__ wwp,
    const float* __restrict__ ctrl, const float* __restrict__ part,
    const float* __restrict__ W, const float* __restrict__ bias,
    float* __restrict__ out, float* __restrict__ o_ro)
{
    int tid = threadIdx.x;

    if (blockIdx.x < 2048) {
        // ---- sweep2: thread-per-row, all 4 head updates ----
        int bc = blockIdx.x; int b = bc >> 3; int nb = (bc & 7) << 8;
        __shared__ float sea[8][64];   // e0..e3, a0..a3
        if (tid < 64) {
            #pragma unroll
            for (int h = 0; h < 4; h++) {
                const float* ph = g_wp + ((size_t)h*B_ + b)*PW_;
                sea[h][tid]   = sigmoidf(ph[70 + tid]);
                sea[4+h][tid] = tanhf(ph[134 + tid]);
            }
        }
        __syncthreads();

        const size_t P = (size_t)B_*N_;
        size_t ix = (size_t)b*N_ + nb + tid;
        float w[4];
        #pragma unroll
        for (int h = 0; h < 4; h++) w[h] = wwp[(size_t)h*P + ix];

        const float4* src = (const float4*)(mem_in + ix*M_);
        float4* dst = (float4*)(mem_out + ix*M_);
        #pragma unroll
        for (int mb = 0; mb < 16; mb++) {
            float4 d = src[mb];
            float4 ec[4], ac[4];
            #pragma unroll
            for (int h = 0; h < 4; h++) {
                ec[h] = *(const float4*)&sea[h][mb*4];
                ac[h] = *(const float4*)&sea[4+h][mb*4];
            }
            float vv[4] = {d.x, d.y, d.z, d.w};
            #pragma unroll
            for (int j = 0; j < 4; j++) {
                float m = vv[j];
                #pragma unroll
                for (int h = 0; h < 4; h++) {
                    float eh = ((const float*)&ec[h])[j];
                    float ah = ((const float*)&ac[h])[j];
                    m = m*(1.f - w[h]*eh) + w[h]*ah;
                }
                vv[j] = m;
            }
            dst[mb] = make_float4(vv[0], vv[1], vv[2], vv[3]);
        }
    } else {
        // ---- output GEMM with fused ro-sum: A = [ctrl | sum8(ro_part)] ----
        __shared__ float As[32][33];
        __shared__ float Ws[32][64];
        constexpr int Nc = 256;
        int t = blockIdx.x - 2048;
        int cx = t & 3, ry = t >> 2;
        int col0 = cx * 64;
        int row0 = ry * 32;
        int tx = tid & 15, ty = tid >> 4;
        float acc[2][4] = {};

        for (int k0 = 0; k0 < 768; k0 += 32) {
            {
                int m  = tid >> 3;
                int kk = (tid & 7) * 4;
                int r = row0 + m, c = k0 + kk;
                float4 v;
                if (c < 512) {
                    v = *(const float4*)(ctrl + (size_t)r*512 + c);
                } else {
                    int cc = c - 512;
                    const float* p = part + (size_t)r*256 + cc;
                    v = *(const float4*)p;
                    #pragma unroll
                    for (int q = 1; q < 8; q++) {
                        float4 vq = *(const float4*)(p + (size_t)q*B_*256);
                        v.x += vq.x; v.y += vq.y; v.z += vq.z; v.w += vq.w;
                    }
                    if (cx == 0)
                        *(float4*)(o_ro + (size_t)r*256 + cc) = v;
                }
                As[m][kk] = v.x; As[m][kk+1] = v.y; As[m][kk+2] = v.z; As[m][kk+3] = v.w;
            }
            {
                int kk = tid >> 3;
                int n0 = (tid & 7) * 8;
                const float* wrow = W + (size_t)(k0 + kk)*Nc + col0 + n0;
                #pragma unroll
                for (int j = 0; j < 8; j++)
                    Ws[kk][n0 + j] = wrow[j];
            }
            __syncthreads();
            #pragma unroll
            for (int kk = 0; kk < 32; kk++) {
                float a0 = As[ty*2 + 0][kk];
                float a1 = As[ty*2 + 1][kk];
                float4 w4 = *(const float4*)&Ws[kk][tx*4];
                acc[0][0] += a0*w4.x; acc[0][1] += a0*w4.y; acc[0][2] += a0*w4.z; acc[0][3] += a0*w4.w;
                acc[1][0] += a1*w4.x; acc[1][1] += a1*w4.y; acc[1][2] += a1*w4.z; acc[1][3] += a1*w4.w;
            }
            __syncthreads();
        }
        #pragma unroll
        for (int i = 0; i < 2; i++) {
            int gm = row0 + ty*2 + i;
            #pragma unroll
            for (int j = 0; j < 4; j++) {
                int gn = col0 + tx*4 + j;
                out[(size_t)gm*Nc + gn] = acc[i][j] + bias[gn];
            }
        }
    }
}

// ---------------- host launcher ----------------
extern "C" void kernel_launch(void* const* d_in, const int* in_sizes, int n_in,
                              void* d_out, int out_size)
{
    const float* ext    = (const float*)d_in[0];
    const float* pread  = (const float*)d_in[1];
    const float* prw    = (const float*)d_in[2];
    const float* pww    = (const float*)d_in[3];
    const float* mem    = (const float*)d_in[4];
    const float* ctrlW  = (const float*)d_in[5];
    const float* ctrlb  = (const float*)d_in[6];
    const float* readW  = (const float*)d_in[7];
    const float* readb  = (const float*)d_in[8];
    const float* writeW = (const float*)d_in[9];
    const float* writeb = (const float*)d_in[10];
    const float* outW   = (const float*)d_in[11];
    const float* outb   = (const float*)d_in[12];
    float* out = (float*)d_out;

    float *ctrl, *rp, *wp, *ropart;
    cudaGetSymbolAddress((void**)&ctrl,   g_ctrl);
    cudaGetSymbolAddress((void**)&rp,     g_rp);
    cudaGetSymbolAddress((void**)&wp,     g_wp);
    cudaGetSymbolAddress((void**)&ropart, g_ropart);

    float* o_mem = out + OUT_MEM;
    float* o_ro  = out + OUT_RO;
    float* o_rw  = out + OUT_RW;
    float* o_ww  = out + OUT_WW;

    // Controller GEMM with fused concat
    gemm_cat_kernel<<<dim3(8, 8), 256>>>(ext, 256, pread, 256, ctrlW, ctrlb, ctrl, 512);

    // All 8 head parameter GEMMs in one launch
    gemm_heads_kernel<<<dim3(4, 8, 8), 256>>>(ctrl, readW, readb, rp, writeW, writeb, wp);

    // Pass A (thread-per-row)
    passA_kernel<<<2048, 256>>>(mem);

    // Addressing: 4 read heads + write heads 0&1
    address5_kernel<<<dim3(256, 5), 512>>>(prw, pww, o_rw, o_ww);

    // Sweep 1: stats (thread-per-row) + reads einsum (lane-per-m)
    sweep1_kernel<<<2048, 256>>>(mem, o_rw, o_ww, ropart);

    // Write heads 2 & 3
    addr23_kernel<<<256, 512>>>(pww, o_ww);

    // Fused tail: sweep2 (thread-per-row) + output GEMM (with 8-plane ro-sum)
    tail_kernel<<<2080, 256>>>(mem, o_mem, o_ww, ctrl, ropart, outW, outb, out, o_ro);
}

// round 14
// speedup vs baseline: 1.2185x; 1.2185x over previous
#include <cuda_runtime.h>
#include <math.h>

// Problem constants
constexpr int B_  = 256;
constexpr int N_  = 2048;
constexpr int M_  = 64;
constexpr int C_  = 512;
constexpr int PR_ = 70;   // M + 3 + SHIFT
constexpr int PW_ = 198;  // PR + 2M
constexpr float EPSF = 1e-8f;

// Output layout (floats): ntm_out, memory, read_out, new_read_w, new_write_w
constexpr size_t OUT_MEM = 65536;
constexpr size_t OUT_RO  = 33619968;
constexpr size_t OUT_RW  = 33685504;
constexpr size_t OUT_WW  = 35782656;

// ---------------- device scratch ----------------
__device__ float g_ctrl[B_*C_];
__device__ float g_rp  [4*B_*PR_];
__device__ float g_wp  [4*B_*PW_];
__device__ float g_dot [5*(size_t)B_*N_];
__device__ float g_norm[(size_t)B_*N_];
__device__ float g_base[6*(size_t)B_*N_];   // base dots: Da,Db,S1,S2,T0,T1
__device__ float g_ropart[8*B_*256];

__device__ __forceinline__ float softplusf(float x){ return x > 20.f ? x : log1pf(expf(x)); }
__device__ __forceinline__ float sigmoidf (float x){ return 1.f/(1.f+expf(-x)); }

// ---------------- GEMM body (proven): tile 32x64, K-step 32, 256 threads ----------------
__device__ __forceinline__ void gemm_body(
    const float* __restrict__ A0, int ca,
    const float* __restrict__ A1, int cb,
    const float* __restrict__ W, const float* __restrict__ bias,
    float* __restrict__ out, int Nc)
{
    int col0 = blockIdx.x * 64;
    if (col0 >= Nc) return;
    int row0 = blockIdx.y * 32;
    int K = ca + cb;

    __shared__ float As[32][33];
    __shared__ float Ws[32][64];
    int tid = threadIdx.x;
    int tx = tid & 15, ty = tid >> 4;
    float acc[2][4] = {};

    for (int k0 = 0; k0 < K; k0 += 32) {
        {
            int m  = tid >> 3;
            int kk = (tid & 7) * 4;
            int r = row0 + m, c = k0 + kk;
            float4 v;
            if (c < ca) v = *(const float4*)(A0 + (size_t)r*ca + c);
            else        v = *(const float4*)(A1 + (size_t)r*cb + (c - ca));
            As[m][kk] = v.x; As[m][kk+1] = v.y; As[m][kk+2] = v.z; As[m][kk+3] = v.w;
        }
        {
            int kk = tid >> 3;
            int n0 = (tid & 7) * 8;
            const float* wrow = W + (size_t)(k0 + kk)*Nc + col0 + n0;
            #pragma unroll
            for (int j = 0; j < 8; j++) {
                int gn = col0 + n0 + j;
                Ws[kk][n0 + j] = (gn < Nc) ? wrow[j] : 0.f;
            }
        }
        __syncthreads();
        #pragma unroll
        for (int kk = 0; kk < 32; kk++) {
            float a0 = As[ty*2 + 0][kk];
            float a1 = As[ty*2 + 1][kk];
            float4 w4 = *(const float4*)&Ws[kk][tx*4];
            acc[0][0] += a0*w4.x; acc[0][1] += a0*w4.y; acc[0][2] += a0*w4.z; acc[0][3] += a0*w4.w;
            acc[1][0] += a1*w4.x; acc[1][1] += a1*w4.y; acc[1][2] += a1*w4.z; acc[1][3] += a1*w4.w;
        }
        __syncthreads();
    }
    #pragma unroll
    for (int i = 0; i < 2; i++) {
        int gm = row0 + ty*2 + i;
        #pragma unroll
        for (int j = 0; j < 4; j++) {
            int gn = col0 + tx*4 + j;
            if (gn < Nc) out[(size_t)gm*Nc + gn] = acc[i][j] + bias[gn];
        }
    }
}

__global__ void gemm_cat_kernel(const float* __restrict__ A0, int ca,
                                const float* __restrict__ A1, int cb,
                                const float* __restrict__ W, const float* __restrict__ bias,
                                float* __restrict__ out, int Nc)
{
    gemm_body(A0, ca, A1, cb, W, bias, out, Nc);
}

__global__ void gemm_heads_kernel(const float* __restrict__ ctrl,
                                  const float* __restrict__ readW, const float* __restrict__ readb,
                                  float* __restrict__ rp,
                                  const float* __restrict__ writeW, const float* __restrict__ writeb,
                                  float* __restrict__ wp)
{
    int h = blockIdx.z;
    const float *W, *bias; float* out; int Nc;
    if (h < 4) {
        W = readW + (size_t)h*C_*PR_; bias = readb + h*PR_;
        out = rp + (size_t)h*B_*PR_;  Nc = PR_;
    } else {
        int g = h - 4;
        W = writeW + (size_t)g*C_*PW_; bias = writeb + g*PW_;
        out = wp + (size_t)g*B_*PW_;   Nc = PW_;
    }
    gemm_body(ctrl, C_, nullptr, 0, W, bias, out, Nc);
}

// ---------------- Pass A: thread-per-row, smem constants, zero shuffles ----------------
__global__ void __launch_bounds__(256) passA_kernel(const float* __restrict__ mem)
{
    int bc = blockIdx.x; int b = bc >> 3; int nb = (bc & 7) << 8;
    int tid = threadIdx.x;

    __shared__ float cst[11][64];
    for (int i = tid; i < 5*64; i += 256) {
        int h = i >> 6, m = i & 63;
        cst[h][m] = (h < 4) ? g_rp[((size_t)h*B_ + b)*PR_ + m]
                            : g_wp[(size_t)b*PW_ + m];
    }
    if (tid < 64) {
        const float* wp0 = g_wp + (size_t)b*PW_;
        const float* wp1 = g_wp + ((size_t)B_ + b)*PW_;
        float e0 = sigmoidf(wp0[70 + tid]);
        float a0 = tanhf(wp0[134 + tid]);
        float k1 = wp1[tid];
        cst[5][tid]  = k1;
        cst[6][tid]  = e0*k1;
        cst[7][tid]  = e0;
        cst[8][tid]  = e0*e0;
        cst[9][tid]  = a0;
        cst[10][tid] = e0*a0;
    }
    __syncthreads();

    size_t ix = (size_t)b*N_ + nb + tid;
    const float4* rp4 = (const float4*)(mem + ix*M_);

    float acc[12] = {};
    #pragma unroll
    for (int mb = 0; mb < 16; mb++) {
        float4 d = rp4[mb];
        float4 c[11];
        #pragma unroll
        for (int ci = 0; ci < 11; ci++)
            c[ci] = *(const float4*)&cst[ci][mb*4];
        float vv[4] = {d.x, d.y, d.z, d.w};
        #pragma unroll
        for (int j = 0; j < 4; j++) {
            float v  = vv[j];
            float vs = v*v;
            acc[0]  += vs;
            acc[1]  += v * ((const float*)&c[0])[j];
            acc[2]  += v * ((const float*)&c[1])[j];
            acc[3]  += v * ((const float*)&c[2])[j];
            acc[4]  += v * ((const float*)&c[3])[j];
            acc[5]  += v * ((const float*)&c[4])[j];
            acc[6]  += v * ((const float*)&c[5])[j];
            acc[7]  += v * ((const float*)&c[6])[j];
            acc[8]  += vs * ((const float*)&c[7])[j];
            acc[9]  += vs * ((const float*)&c[8])[j];
            acc[10] += v * ((const float*)&c[9])[j];
            acc[11] += v * ((const float*)&c[10])[j];
        }
    }

    const size_t P = (size_t)B_*N_;
    g_norm[ix] = sqrtf(acc[0]);
    #pragma unroll
    for (int h = 0; h < 5; h++) g_dot[(size_t)h*P + ix] = acc[1+h];
    #pragma unroll
    for (int r = 0; r < 6; r++) g_base[(size_t)r*P + ix] = acc[6+r];
}

// ---------------- block reduction helpers (512 threads) ----------------
__device__ __forceinline__ float block_reduce_sum512(float v, float* sbuf)
{
    int tid = threadIdx.x;
    #pragma unroll
    for (int o = 16; o > 0; o >>= 1) v += __shfl_xor_sync(0xffffffffu, v, o);
    if ((tid & 31) == 0) sbuf[tid >> 5] = v;
    __syncthreads();
    if (tid < 32) {
        float x = (tid < 16) ? sbuf[tid] : 0.f;
        #pragma unroll
        for (int o = 8; o > 0; o >>= 1) x += __shfl_xor_sync(0xffffffffu, x, o);
        if (tid == 0) sbuf[0] = x;
    }
    __syncthreads();
    float r = sbuf[0];
    __syncthreads();
    return r;
}

__device__ __forceinline__ float block_reduce_max512(float v, float* sbuf)
{
    int tid = threadIdx.x;
    #pragma unroll
    for (int o = 16; o > 0; o >>= 1) v = fmaxf(v, __shfl_xor_sync(0xffffffffu, v, o));
    if ((tid & 31) == 0) sbuf[tid >> 5] = v;
    __syncthreads();
    if (tid < 32) {
        float x = (tid < 16) ? sbuf[tid] : -3.4e38f;
        #pragma unroll
        for (int o = 8; o > 0; o >>= 1) x = fmaxf(x, __shfl_xor_sync(0xffffffffu, x, o));
        if (tid == 0) sbuf[0] = x;
    }
    __syncthreads();
    float r = sbuf[0];
    __syncthreads();
    return r;
}

// ---------------- addressing tail (512 threads, 4 items/thread) ----------------
__device__ __forceinline__ void address_tail(
    float* x, float g, float s0, float s1, float s2, float gamma,
    const float* __restrict__ wpb, float* __restrict__ woutb,
    float* wg, float* rbuf)
{
    int tid = threadIdx.x;
    float mx = fmaxf(fmaxf(x[0], x[1]), fmaxf(x[2], x[3]));
    float bmax = block_reduce_max512(mx, rbuf);
    float lsum = 0.f;
    #pragma unroll
    for (int i = 0; i < 4; i++) {
        float e = __expf(x[i] - bmax);
        wg[tid + i*512] = e;
        lsum += e;
    }
    float bsum = block_reduce_sum512(lsum, rbuf);
    float inv = 1.f / bsum;
    #pragma unroll
    for (int i = 0; i < 4; i++) {
        int n = tid + i*512;
        wg[n] = g * (wg[n]*inv) + (1.f-g) * wpb[n];
    }
    __syncthreads();
    float wpow[4];
    lsum = 0.f;
    #pragma unroll
    for (int i = 0; i < 4; i++) {
        int n = tid + i*512;
        float ws = s0*wg[(n+1)&(N_-1)] + s1*wg[n] + s2*wg[(n-1)&(N_-1)];
        float t = __powf(ws + EPSF, gamma);
        wpow[i] = t;
        lsum += t;
    }
    float psum = block_reduce_sum512(lsum, rbuf);
    float ip = 1.f / psum;
    #pragma unroll
    for (int i = 0; i < 4; i++) {
        float wv = wpow[i]*ip;
        woutb[tid + i*512] = wv;
        x[i] = wv;
    }
}

__device__ __forceinline__ void head_scalars(const float* __restrict__ p, float ksum, float* sc)
{
    sc[0] = sqrtf(ksum);
    sc[1] = softplusf(p[64]);
    sc[2] = sigmoidf(p[65]);
    float a0 = p[66], a1 = p[67], a2 = p[68];
    float mx = fmaxf(a0, fmaxf(a1, a2));
    float e0 = expf(a0-mx), e1 = expf(a1-mx), e2 = expf(a2-mx);
    float es = e0 + e1 + e2;
    sc[3] = e0/es; sc[4] = e1/es; sc[5] = e2/es;
    sc[6] = 1.f + softplusf(p[69]);
}

__device__ __forceinline__ void poly_x(
    float* x, const float* wdone, size_t base,
    float CC, float UU, float knorm, float beta)
{
    int tid = threadIdx.x;
    const size_t P = (size_t)B_*N_;
    const float* nrmp = g_norm + base;
    #pragma unroll
    for (int i = 0; i < 4; i++) {
        int n = tid + i*512;
        float w  = wdone[i];
        float Da = g_base[0*P + base + n];
        float Db = g_base[1*P + base + n];
        float S1 = g_base[2*P + base + n];
        float S2 = g_base[3*P + base + n];
        float T0 = g_base[4*P + base + n];
        float T1 = g_base[5*P + base + n];
        float nr = nrmp[n];
        float S0 = nr*nr;
        float dotv = Da - w*Db + w*CC;
        float w2 = w*w;
        float nsq = S0 - 2.f*w*S1 + w2*S2 + 2.f*w*T0 - 2.f*w2*T1 + w2*UU;
        float nn = sqrtf(fmaxf(nsq, 0.f));
        x[i] = beta * (dotv / (nn*knorm + EPSF));
    }
}

// ---------------- fused addressing: 4 read heads (y=0..3) + write heads 0&1 (y=4) -------------
__global__ void __launch_bounds__(512) address5_kernel(
    const float* __restrict__ prw,
    const float* __restrict__ pww,
    float* __restrict__ o_rw,
    float* __restrict__ o_ww)
{
    __shared__ float wg[2048];
    __shared__ float rbuf[32];
    __shared__ float sc[16];
    int b = blockIdx.x, h = blockIdx.y, tid = threadIdx.x;
    size_t base = (size_t)b*N_;
    const size_t P = (size_t)B_*N_;

    if (h < 4) {
        const float* p = g_rp + ((size_t)h*B_ + b)*PR_;
        float kv = 0.f;
        if (tid < 64) { float xx = p[tid]; kv = xx*xx; }
        float ksum = block_reduce_sum512(kv, rbuf);
        if (tid == 0) head_scalars(p, ksum, sc);
        __syncthreads();
        float knorm = sc[0], beta = sc[1], g = sc[2];
        float s0 = sc[3], s1 = sc[4], s2 = sc[5], gamma = sc[6];

        const float* dotb = g_dot + (size_t)h*P + base;
        const float* nrmb = g_norm + base;
        float x[4];
        #pragma unroll
        for (int i = 0; i < 4; i++) {
            int n = tid + i*512;
            x[i] = beta * (dotb[n] / (nrmb[n]*knorm + EPSF));
        }
        address_tail(x, g, s0, s1, s2, gamma,
                     prw + (size_t)h*P + base, o_rw + (size_t)h*P + base, wg, rbuf);
    } else {
        const float* p0 = g_wp + (size_t)b*PW_;
        const float* p1 = g_wp + ((size_t)1*B_ + b)*PW_;
        float kv0 = 0.f, kv1 = 0.f, c1 = 0.f, c2 = 0.f;
        if (tid < 64) {
            float k0 = p0[tid], k1 = p1[tid];
            float a0 = tanhf(p0[134 + tid]);
            kv0 = k0*k0; kv1 = k1*k1; c1 = a0*k1; c2 = a0*a0;
        }
        float ks0 = block_reduce_sum512(kv0, rbuf);
        float ks1 = block_reduce_sum512(kv1, rbuf);
        float Cc  = block_reduce_sum512(c1, rbuf);
        float U   = block_reduce_sum512(c2, rbuf);
        if (tid == 0) {
            head_scalars(p0, ks0, sc);
            head_scalars(p1, ks1, sc + 7);
            sc[14] = Cc; sc[15] = U;
        }
        __syncthreads();

        float knorm = sc[0], beta = sc[1], g = sc[2];
        float s0 = sc[3], s1 = sc[4], s2 = sc[5], gamma = sc[6];
        const float* dotb = g_dot + 4*P + base;
        const float* nrmb = g_norm + base;
        float x[4];
        #pragma unroll
        for (int i = 0; i < 4; i++) {
            int n = tid + i*512;
            x[i] = beta * (dotb[n] / (nrmb[n]*knorm + EPSF));
        }
        address_tail(x, g, s0, s1, s2, gamma, pww + base, o_ww + base, wg, rbuf);
        __syncthreads();
        float y[4];
        poly_x(y, x, base, sc[14], sc[15], sc[7], sc[8]);
        address_tail(y, sc[9], sc[10], sc[11], sc[12], sc[13],
                     pww + P + base, o_ww + P + base, wg, rbuf);
    }
}

// ---------------- fused write heads 2 & 3 ----------------
__global__ void __launch_bounds__(512) addr23_kernel(
    const float* __restrict__ pww,
    float* __restrict__ o_ww)
{
    __shared__ float wg[2048];
    __shared__ float rbuf[32];
    __shared__ float sc[16];
    int b = blockIdx.x, tid = threadIdx.x;
    size_t base = (size_t)b*N_;
    const size_t P = (size_t)B_*N_;

    const float* p2 = g_wp + ((size_t)2*B_ + b)*PW_;
    const float* p3 = g_wp + ((size_t)3*B_ + b)*PW_;
    float kv2 = 0.f, kv3 = 0.f, c1 = 0.f, c2 = 0.f;
    if (tid < 64) {
        float k2 = p2[tid], k3 = p3[tid];
        float a2 = tanhf(p2[134 + tid]);
        kv2 = k2*k2; kv3 = k3*k3; c1 = a2*k3; c2 = a2*a2;
    }
    float ks2 = block_reduce_sum512(kv2, rbuf);
    float ks3 = block_reduce_sum512(kv3, rbuf);
    float Cc  = block_reduce_sum512(c1, rbuf);
    float U   = block_reduce_sum512(c2, rbuf);
    if (tid == 0) {
        head_scalars(p2, ks2, sc);
        head_scalars(p3, ks3, sc + 7);
        sc[14] = Cc; sc[15] = U;
    }
    __syncthreads();

    float knorm = sc[0], beta = sc[1], g = sc[2];
    float s0 = sc[3], s1 = sc[4], s2 = sc[5], gamma = sc[6];
    const float* dotb = g_dot + 4*P + base;
    const float* nrmb = g_norm + base;
    float x[4];
    #pragma unroll
    for (int i = 0; i < 4; i++) {
        int n = tid + i*512;
        x[i] = beta * (dotb[n] / (nrmb[n]*knorm + EPSF));
    }
    address_tail(x, g, s0, s1, s2, gamma, pww + 2*P + base, o_ww + 2*P + base, wg, rbuf);
    __syncthreads();
    float y[4];
    poly_x(y, x, base, sc[14], sc[15], sc[7], sc[8]);
    address_tail(y, sc[9], sc[10], sc[11], sc[12], sc[13],
                 pww + 3*P + base, o_ww + 3*P + base, wg, rbuf);
}

// ---------------- Sweep 1 (two-phase thread-per-row): stats + reads einsum ----------------
__global__ void __launch_bounds__(256) sweep1_kernel(
    const float* __restrict__ mem_in,
    const float* __restrict__ wr,
    const float* __restrict__ wwp,
    float* __restrict__ ro_part)
{
    int bc = blockIdx.x; int b = bc >> 3; int nb = (bc & 7) << 8;
    int tid = threadIdx.x, wid = tid >> 5, lane = tid & 31;
    const size_t P = (size_t)B_*N_;

    __shared__ float cst[11][64];
    __shared__ float ws4[256][4];
    __shared__ float2 sred[8][4][32];
    if (tid < 64) {
        const float* p0 = g_wp + (size_t)b*PW_;
        const float* p1 = g_wp + ((size_t)1*B_ + b)*PW_;
        const float* p2 = g_wp + ((size_t)2*B_ + b)*PW_;
        const float* p3 = g_wp + ((size_t)3*B_ + b)*PW_;
        float e2 = sigmoidf(p2[70 + tid]);
        float a2 = tanhf(p2[134 + tid]);
        float k3 = p3[tid];
        cst[0][tid]  = p2[tid];
        cst[1][tid]  = e2*k3;
        cst[2][tid]  = e2;
        cst[3][tid]  = e2*e2;
        cst[4][tid]  = a2;
        cst[5][tid]  = e2*a2;
        cst[6][tid]  = k3;
        cst[7][tid]  = sigmoidf(p0[70 + tid]);
        cst[8][tid]  = tanhf(p0[134 + tid]);
        cst[9][tid]  = sigmoidf(p1[70 + tid]);
        cst[10][tid] = tanhf(p1[134 + tid]);
    }
    size_t ix = (size_t)b*N_ + nb + tid;
    #pragma unroll
    for (int h = 0; h < 4; h++) ws4[tid][h] = wr[(size_t)h*P + ix];
    __syncthreads();

    // phase 1: per-row stats
    float w0 = wwp[ix], w1 = wwp[P + ix];
    const float4* rp4 = (const float4*)(mem_in + ix*M_);
    float acc[8] = {};
    #pragma unroll
    for (int mb = 0; mb < 16; mb++) {
        float4 d = rp4[mb];
        float4 c[11];
        #pragma unroll
        for (int ci = 0; ci < 11; ci++)
            c[ci] = *(const float4*)&cst[ci][mb*4];
        float vv[4] = {d.x, d.y, d.z, d.w};
        #pragma unroll
        for (int j = 0; j < 4; j++) {
            float v  = vv[j];
            float e0 = ((const float*)&c[7])[j], a0 = ((const float*)&c[8])[j];
            float e1 = ((const float*)&c[9])[j], a1 = ((const float*)&c[10])[j];
            float m1 = v*(1.f - w0*e0) + w0*a0;
            float m2 = m1*(1.f - w1*e1) + w1*a1;
            float s  = m2*m2;
            acc[0] += m2 * ((const float*)&c[0])[j];
            acc[1] += s;
            acc[2] += m2 * ((const float*)&c[6])[j];
            acc[3] += m2 * ((const float*)&c[1])[j];
            acc[4] += s  * ((const float*)&c[2])[j];
            acc[5] += s  * ((const float*)&c[3])[j];
            acc[6] += m2 * ((const float*)&c[4])[j];
            acc[7] += m2 * ((const float*)&c[5])[j];
        }
    }
    g_dot[4*P + ix] = acc[0];
    g_norm[ix] = sqrtf(acc[1]);
    #pragma unroll
    for (int r = 0; r < 6; r++) g_base[(size_t)r*P + ix] = acc[2+r];

    // phase 2: reads einsum (lane-per-m, L2-hot re-read)
    float2 racc[4] = {{0,0},{0,0},{0,0},{0,0}};
    size_t rowbase = (size_t)b*N_ + nb + wid*32;
    #pragma unroll 4
    for (int r = 0; r < 32; r++) {
        float2 v2 = *(const float2*)(mem_in + (rowbase + r)*M_ + 2*lane);
        float4 w4 = *(const float4*)&ws4[wid*32 + r][0];
        racc[0].x += w4.x*v2.x; racc[0].y += w4.x*v2.y;
        racc[1].x += w4.y*v2.x; racc[1].y += w4.y*v2.y;
        racc[2].x += w4.z*v2.x; racc[2].y += w4.z*v2.y;
        racc[3].x += w4.w*v2.x; racc[3].y += w4.w*v2.y;
    }
    #pragma unroll
    for (int h = 0; h < 4; h++) sred[wid][h][lane] = racc[h];
    __syncthreads();
    int h = tid >> 6, m = tid & 63;
    int l = m >> 1, c = m & 1;
    float s = 0.f;
    #pragma unroll
    for (int w = 0; w < 8; w++) {
        float2 t = sred[w][h][l];
        s += c ? t.y : t.x;
    }
    ro_part[(size_t)(bc & 7)*B_*256 + (size_t)b*256 + h*64 + m] = s;
}

// ---------------- Fused tail: out GEMM (blocks 0..31) + sweep2 half-warp (blocks 32..1055) ----
__global__ void __launch_bounds__(256) tail_kernel(
    const float* __restrict__ mem_in, float* __restrict__ mem_out,
    const float* __restrict__ wwp,
    const float* __restrict__ ctrl, const float* __restrict__ part,
    const float* __restrict__ W, const float* __restrict__ bias,
    float* __restrict__ out, float* __restrict__ o_ro)
{
    __shared__ float As[32][33];
    __shared__ float Ws[32][64];
    int tid = threadIdx.x;

    if (blockIdx.x >= 32) {
        // ---- sweep2: all 4 head updates, half-warp float4 (coalesced stores) ----
        int bc = blockIdx.x - 32; int b = bc >> 2; int nb = (bc & 3) << 9;
        int wid = tid >> 5, lane = tid & 31;
        int hw = lane >> 4, l16 = lane & 15;

        float e[4][4], a[4][4];
        #pragma unroll
        for (int h = 0; h < 4; h++) {
            const float* ph = g_wp + ((size_t)h*B_ + b)*PW_;
            #pragma unroll
            for (int j = 0; j < 4; j++) {
                int m = l16*4 + j;
                e[h][j] = sigmoidf(ph[70 + m]);
                a[h][j] = tanhf(ph[134 + m]);
            }
        }

        const size_t P = (size_t)B_*N_;
        for (int it = 0; it < 32; it += 4) {
            int r0 = it*16 + wid*2 + hw;
            size_t ix[4];
            float4 v[4];
            #pragma unroll
            for (int q = 0; q < 4; q++) {
                ix[q] = (size_t)b*N_ + nb + r0 + q*16;
                v[q] = *(const float4*)(mem_in + ix[q]*M_ + l16*4);
            }
            float w[4][4];
            #pragma unroll
            for (int q = 0; q < 4; q++)
                #pragma unroll
                for (int h = 0; h < 4; h++)
                    w[q][h] = wwp[(size_t)h*P + ix[q]];

            #pragma unroll
            for (int q = 0; q < 4; q++) {
                float vv[4] = {v[q].x, v[q].y, v[q].z, v[q].w};
                #pragma unroll
                for (int j = 0; j < 4; j++) {
                    float m = vv[j];
                    #pragma unroll
                    for (int h = 0; h < 4; h++)
                        m = m*(1.f - w[q][h]*e[h][j]) + w[q][h]*a[h][j];
                    vv[j] = m;
                }
                *(float4*)(mem_out + ix[q]*M_ + l16*4) = make_float4(vv[0], vv[1], vv[2], vv[3]);
            }
        }
    } else {
        // ---- output GEMM with fused ro-sum: A = [ctrl | sum8(ro_part)] ----
        constexpr int Nc = 256;
        int t = blockIdx.x;            // 0..31
        int cx = t & 3, ry = t >> 2;
        int col0 = cx * 64;
        int row0 = ry * 32;
        int tx = tid & 15, ty = tid >> 4;
        float acc[2][4] = {};

        for (int k0 = 0; k0 < 768; k0 += 32) {
            {
                int m  = tid >> 3;
                int kk = (tid & 7) * 4;
                int r = row0 + m, c = k0 + kk;
                float4 v;
                if (c < 512) {
                    v = *(const float4*)(ctrl + (size_t)r*512 + c);
                } else {
                    int cc = c - 512;
                    const float* p = part + (size_t)r*256 + cc;
                    v = *(const float4*)p;
                    #pragma unroll
                    for (int q = 1; q < 8; q++) {
                        float4 vq = *(const float4*)(p + (size_t)q*B_*256);
                        v.x += vq.x; v.y += vq.y; v.z += vq.z; v.w += vq.w;
                    }
                    if (cx == 0)
                        *(float4*)(o_ro + (size_t)r*256 + cc) = v;
                }
                As[m][kk] = v.x; As[m][kk+1] = v.y; As[m][kk+2] = v.z; As[m][kk+3] = v.w;
            }
            {
                int kk = tid >> 3;
                int n0 = (tid & 7) * 8;
                const float* wrow = W + (size_t)(k0 + kk)*Nc + col0 + n0;
                #pragma unroll
                for (int j = 0; j < 8; j++)
                    Ws[kk][n0 + j] = wrow[j];
            }
            __syncthreads();
            #pragma unroll
            for (int kk = 0; kk < 32; kk++) {
                float a0 = As[ty*2 + 0][kk];
                float a1 = As[ty*2 + 1][kk];
                float4 w4 = *(const float4*)&Ws[kk][tx*4];
                acc[0][0] += a0*w4.x; acc[0][1] += a0*w4.y; acc[0][2] += a0*w4.z; acc[0][3] += a0*w4.w;
                acc[1][0] += a1*w4.x; acc[1][1] += a1*w4.y; acc[1][2] += a1*w4.z; acc[1][3] += a1*w4.w;
            }
            __syncthreads();
        }
        #pragma unroll
        for (int i = 0; i < 2; i++) {
            int gm = row0 + ty*2 + i;
            #pragma unroll
            for (int j = 0; j < 4; j++) {
                int gn = col0 + tx*4 + j;
                out[(size_t)gm*Nc + gn] = acc[i][j] + bias[gn];
            }
        }
    }
}

// ---------------- host launcher ----------------
extern "C" void kernel_launch(void* const* d_in, const int* in_sizes, int n_in,
                              void* d_out, int out_size)
{
    const float* ext    = (const float*)d_in[0];
    const float* pread  = (const float*)d_in[1];
    const float* prw    = (const float*)d_in[2];
    const float* pww    = (const float*)d_in[3];
    const float* mem    = (const float*)d_in[4];
    const float* ctrlW  = (const float*)d_in[5];
    const float* ctrlb  = (const float*)d_in[6];
    const float* readW  = (const float*)d_in[7];
    const float* readb  = (const float*)d_in[8];
    const float* writeW = (const float*)d_in[9];
    const float* writeb = (const float*)d_in[10];
    const float* outW   = (const float*)d_in[11];
    const float* outb   = (const float*)d_in[12];
    float* out = (float*)d_out;

    float *ctrl, *rp, *wp, *ropart;
    cudaGetSymbolAddress((void**)&ctrl,   g_ctrl);
    cudaGetSymbolAddress((void**)&rp,     g_rp);
    cudaGetSymbolAddress((void**)&wp,     g_wp);
    cudaGetSymbolAddress((void**)&ropart, g_ropart);

    float* o_mem = out + OUT_MEM;
    float* o_ro  = out + OUT_RO;
    float* o_rw  = out + OUT_RW;
    float* o_ww  = out + OUT_WW;

    // Controller GEMM with fused concat
    gemm_cat_kernel<<<dim3(8, 8), 256>>>(ext, 256, pread, 256, ctrlW, ctrlb, ctrl, 512);

    // All 8 head parameter GEMMs in one launch
    gemm_heads_kernel<<<dim3(4, 8, 8), 256>>>(ctrl, readW, readb, rp, writeW, writeb, wp);

    // Pass A (thread-per-row)
    passA_kernel<<<2048, 256>>>(mem);

    // Addressing: 4 read heads + write heads 0&1
    address5_kernel<<<dim3(256, 5), 512>>>(prw, pww, o_rw, o_ww);

    // Sweep 1: stats (thread-per-row) + reads einsum (lane-per-m)
    sweep1_kernel<<<2048, 256>>>(mem, o_rw, o_ww, ropart);

    // Write heads 2 & 3
    addr23_kernel<<<256, 512>>>(pww, o_ww);

    // Fused tail: out GEMM first (long-running), then sweep2 (coalesced stores)
    tail_kernel<<<1056, 256>>>(mem, o_mem, o_ww, ctrl, ropart, outW, outb, out, o_ro);
}

// round 15
// speedup vs baseline: 1.2391x; 1.0168x over previous
#include <cuda_runtime.h>
#include <math.h>

// Problem constants
constexpr int B_  = 256;
constexpr int N_  = 2048;
constexpr int M_  = 64;
constexpr int C_  = 512;
constexpr int PR_ = 70;   // M + 3 + SHIFT
constexpr int PW_ = 198;  // PR + 2M
constexpr float EPSF = 1e-8f;

// Output layout (floats): ntm_out, memory, read_out, new_read_w, new_write_w
constexpr size_t OUT_MEM = 65536;
constexpr size_t OUT_RO  = 33619968;
constexpr size_t OUT_RW  = 33685504;
constexpr size_t OUT_WW  = 35782656;

// ---------------- device scratch ----------------
__device__ float g_ctrl[B_*C_];
__device__ float g_rp  [4*B_*PR_];
__device__ float g_wp  [4*B_*PW_];
__device__ float g_dot [5*(size_t)B_*N_];
__device__ float g_norm[(size_t)B_*N_];
__device__ float g_base[6*(size_t)B_*N_];   // base dots: Da,Db,S1,S2,T0,T1
__device__ float g_ropart[8*B_*256];

__device__ __forceinline__ float softplusf(float x){ return x > 20.f ? x : log1pf(expf(x)); }
__device__ __forceinline__ float sigmoidf (float x){ return 1.f/(1.f+expf(-x)); }

// ---------------- GEMM body (proven): tile 32x64, K-step 32, 256 threads ----------------
__device__ __forceinline__ void gemm_body(
    const float* __restrict__ A0, int ca,
    const float* __restrict__ A1, int cb,
    const float* __restrict__ W, const float* __restrict__ bias,
    float* __restrict__ out, int Nc)
{
    int col0 = blockIdx.x * 64;
    if (col0 >= Nc) return;
    int row0 = blockIdx.y * 32;
    int K = ca + cb;

    __shared__ float As[32][33];
    __shared__ float Ws[32][64];
    int tid = threadIdx.x;
    int tx = tid & 15, ty = tid >> 4;
    float acc[2][4] = {};

    for (int k0 = 0; k0 < K; k0 += 32) {
        {
            int m  = tid >> 3;
            int kk = (tid & 7) * 4;
            int r = row0 + m, c = k0 + kk;
            float4 v;
            if (c < ca) v = *(const float4*)(A0 + (size_t)r*ca + c);
            else        v = *(const float4*)(A1 + (size_t)r*cb + (c - ca));
            As[m][kk] = v.x; As[m][kk+1] = v.y; As[m][kk+2] = v.z; As[m][kk+3] = v.w;
        }
        {
            int kk = tid >> 3;
            int n0 = (tid & 7) * 8;
            const float* wrow = W + (size_t)(k0 + kk)*Nc + col0 + n0;
            #pragma unroll
            for (int j = 0; j < 8; j++) {
                int gn = col0 + n0 + j;
                Ws[kk][n0 + j] = (gn < Nc) ? wrow[j] : 0.f;
            }
        }
        __syncthreads();
        #pragma unroll
        for (int kk = 0; kk < 32; kk++) {
            float a0 = As[ty*2 + 0][kk];
            float a1 = As[ty*2 + 1][kk];
            float4 w4 = *(const float4*)&Ws[kk][tx*4];
            acc[0][0] += a0*w4.x; acc[0][1] += a0*w4.y; acc[0][2] += a0*w4.z; acc[0][3] += a0*w4.w;
            acc[1][0] += a1*w4.x; acc[1][1] += a1*w4.y; acc[1][2] += a1*w4.z; acc[1][3] += a1*w4.w;
        }
        __syncthreads();
    }
    #pragma unroll
    for (int i = 0; i < 2; i++) {
        int gm = row0 + ty*2 + i;
        #pragma unroll
        for (int j = 0; j < 4; j++) {
            int gn = col0 + tx*4 + j;
            if (gn < Nc) out[(size_t)gm*Nc + gn] = acc[i][j] + bias[gn];
        }
    }
}

__global__ void gemm_cat_kernel(const float* __restrict__ A0, int ca,
                                const float* __restrict__ A1, int cb,
                                const float* __restrict__ W, const float* __restrict__ bias,
                                float* __restrict__ out, int Nc)
{
    gemm_body(A0, ca, A1, cb, W, bias, out, Nc);
}

__global__ void gemm_heads_kernel(const float* __restrict__ ctrl,
                                  const float* __restrict__ readW, const float* __restrict__ readb,
                                  float* __restrict__ rp,
                                  const float* __restrict__ writeW, const float* __restrict__ writeb,
                                  float* __restrict__ wp)
{
    int h = blockIdx.z;
    const float *W, *bias; float* out; int Nc;
    if (h < 4) {
        W = readW + (size_t)h*C_*PR_; bias = readb + h*PR_;
        out = rp + (size_t)h*B_*PR_;  Nc = PR_;
    } else {
        int g = h - 4;
        W = writeW + (size_t)g*C_*PW_; bias = writeb + g*PW_;
        out = wp + (size_t)g*B_*PW_;   Nc = PW_;
    }
    gemm_body(ctrl, C_, nullptr, 0, W, bias, out, Nc);
}

// ---------------- Output GEMM with fused ro-sum: A = [ctrl | sum8(ro_part)] ----------------
__global__ void __launch_bounds__(256) gemm_out_kernel(
    const float* __restrict__ ctrl, const float* __restrict__ part,
    const float* __restrict__ W, const float* __restrict__ bias,
    float* __restrict__ out, float* __restrict__ o_ro)
{
    __shared__ float As[32][33];
    __shared__ float Ws[32][64];
    constexpr int Nc = 256;
    int tid = threadIdx.x;
    int cx = blockIdx.x, ry = blockIdx.y;
    int col0 = cx * 64;
    int row0 = ry * 32;
    int tx = tid & 15, ty = tid >> 4;
    float acc[2][4] = {};

    for (int k0 = 0; k0 < 768; k0 += 32) {
        {
            int m  = tid >> 3;
            int kk = (tid & 7) * 4;
            int r = row0 + m, c = k0 + kk;
            float4 v;
            if (c < 512) {
                v = *(const float4*)(ctrl + (size_t)r*512 + c);
            } else {
                int cc = c - 512;
                const float* p = part + (size_t)r*256 + cc;
                v = *(const float4*)p;
                #pragma unroll
                for (int q = 1; q < 8; q++) {
                    float4 vq = *(const float4*)(p + (size_t)q*B_*256);
                    v.x += vq.x; v.y += vq.y; v.z += vq.z; v.w += vq.w;
                }
                if (cx == 0)
                    *(float4*)(o_ro + (size_t)r*256 + cc) = v;
            }
            As[m][kk] = v.x; As[m][kk+1] = v.y; As[m][kk+2] = v.z; As[m][kk+3] = v.w;
        }
        {
            int kk = tid >> 3;
            int n0 = (tid & 7) * 8;
            const float* wrow = W + (size_t)(k0 + kk)*Nc + col0 + n0;
            #pragma unroll
            for (int j = 0; j < 8; j++)
                Ws[kk][n0 + j] = wrow[j];
        }
        __syncthreads();
        #pragma unroll
        for (int kk = 0; kk < 32; kk++) {
            float a0 = As[ty*2 + 0][kk];
            float a1 = As[ty*2 + 1][kk];
            float4 w4 = *(const float4*)&Ws[kk][tx*4];
            acc[0][0] += a0*w4.x; acc[0][1] += a0*w4.y; acc[0][2] += a0*w4.z; acc[0][3] += a0*w4.w;
            acc[1][0] += a1*w4.x; acc[1][1] += a1*w4.y; acc[1][2] += a1*w4.z; acc[1][3] += a1*w4.w;
        }
        __syncthreads();
    }
    #pragma unroll
    for (int i = 0; i < 2; i++) {
        int gm = row0 + ty*2 + i;
        #pragma unroll
        for (int j = 0; j < 4; j++) {
            int gn = col0 + tx*4 + j;
            out[(size_t)gm*Nc + gn] = acc[i][j] + bias[gn];
        }
    }
}

// ---------------- Pass A: thread-per-row, smem constants, zero shuffles ----------------
__global__ void __launch_bounds__(256) passA_kernel(const float* __restrict__ mem)
{
    int bc = blockIdx.x; int b = bc >> 3; int nb = (bc & 7) << 8;
    int tid = threadIdx.x;

    __shared__ float cst[11][64];
    for (int i = tid; i < 5*64; i += 256) {
        int h = i >> 6, m = i & 63;
        cst[h][m] = (h < 4) ? g_rp[((size_t)h*B_ + b)*PR_ + m]
                            : g_wp[(size_t)b*PW_ + m];
    }
    if (tid < 64) {
        const float* wp0 = g_wp + (size_t)b*PW_;
        const float* wp1 = g_wp + ((size_t)B_ + b)*PW_;
        float e0 = sigmoidf(wp0[70 + tid]);
        float a0 = tanhf(wp0[134 + tid]);
        float k1 = wp1[tid];
        cst[5][tid]  = k1;
        cst[6][tid]  = e0*k1;
        cst[7][tid]  = e0;
        cst[8][tid]  = e0*e0;
        cst[9][tid]  = a0;
        cst[10][tid] = e0*a0;
    }
    __syncthreads();

    size_t ix = (size_t)b*N_ + nb + tid;
    const float4* rp4 = (const float4*)(mem + ix*M_);

    float acc[12] = {};
    #pragma unroll
    for (int mb = 0; mb < 16; mb++) {
        float4 d = rp4[mb];
        float4 c[11];
        #pragma unroll
        for (int ci = 0; ci < 11; ci++)
            c[ci] = *(const float4*)&cst[ci][mb*4];
        float vv[4] = {d.x, d.y, d.z, d.w};
        #pragma unroll
        for (int j = 0; j < 4; j++) {
            float v  = vv[j];
            float vs = v*v;
            acc[0]  += vs;
            acc[1]  += v * ((const float*)&c[0])[j];
            acc[2]  += v * ((const float*)&c[1])[j];
            acc[3]  += v * ((const float*)&c[2])[j];
            acc[4]  += v * ((const float*)&c[3])[j];
            acc[5]  += v * ((const float*)&c[4])[j];
            acc[6]  += v * ((const float*)&c[5])[j];
            acc[7]  += v * ((const float*)&c[6])[j];
            acc[8]  += vs * ((const float*)&c[7])[j];
            acc[9]  += vs * ((const float*)&c[8])[j];
            acc[10] += v * ((const float*)&c[9])[j];
            acc[11] += v * ((const float*)&c[10])[j];
        }
    }

    const size_t P = (size_t)B_*N_;
    g_norm[ix] = sqrtf(acc[0]);
    #pragma unroll
    for (int h = 0; h < 5; h++) g_dot[(size_t)h*P + ix] = acc[1+h];
    #pragma unroll
    for (int r = 0; r < 6; r++) g_base[(size_t)r*P + ix] = acc[6+r];
}

// ---------------- block reduction helpers (512 threads) ----------------
__device__ __forceinline__ float block_reduce_sum512(float v, float* sbuf)
{
    int tid = threadIdx.x;
    #pragma unroll
    for (int o = 16; o > 0; o >>= 1) v += __shfl_xor_sync(0xffffffffu, v, o);
    if ((tid & 31) == 0) sbuf[tid >> 5] = v;
    __syncthreads();
    if (tid < 32) {
        float x = (tid < 16) ? sbuf[tid] : 0.f;
        #pragma unroll
        for (int o = 8; o > 0; o >>= 1) x += __shfl_xor_sync(0xffffffffu, x, o);
        if (tid == 0) sbuf[0] = x;
    }
    __syncthreads();
    float r = sbuf[0];
    __syncthreads();
    return r;
}

__device__ __forceinline__ float block_reduce_max512(float v, float* sbuf)
{
    int tid = threadIdx.x;
    #pragma unroll
    for (int o = 16; o > 0; o >>= 1) v = fmaxf(v, __shfl_xor_sync(0xffffffffu, v, o));
    if ((tid & 31) == 0) sbuf[tid >> 5] = v;
    __syncthreads();
    if (tid < 32) {
        float x = (tid < 16) ? sbuf[tid] : -3.4e38f;
        #pragma unroll
        for (int o = 8; o > 0; o >>= 1) x = fmaxf(x, __shfl_xor_sync(0xffffffffu, x, o));
        if (tid == 0) sbuf[0] = x;
    }
    __syncthreads();
    float r = sbuf[0];
    __syncthreads();
    return r;
}

// ---------------- addressing tail (512 threads, 4 items/thread) ----------------
__device__ __forceinline__ void address_tail(
    float* x, float g, float s0, float s1, float s2, float gamma,
    const float* __restrict__ wpb, float* __restrict__ woutb,
    float* wg, float* rbuf)
{
    int tid = threadIdx.x;
    float mx = fmaxf(fmaxf(x[0], x[1]), fmaxf(x[2], x[3]));
    float bmax = block_reduce_max512(mx, rbuf);
    float lsum = 0.f;
    #pragma unroll
    for (int i = 0; i < 4; i++) {
        float e = __expf(x[i] - bmax);
        wg[tid + i*512] = e;
        lsum += e;
    }
    float bsum = block_reduce_sum512(lsum, rbuf);
    float inv = 1.f / bsum;
    #pragma unroll
    for (int i = 0; i < 4; i++) {
        int n = tid + i*512;
        wg[n] = g * (wg[n]*inv) + (1.f-g) * wpb[n];
    }
    __syncthreads();
    float wpow[4];
    lsum = 0.f;
    #pragma unroll
    for (int i = 0; i < 4; i++) {
        int n = tid + i*512;
        float ws = s0*wg[(n+1)&(N_-1)] + s1*wg[n] + s2*wg[(n-1)&(N_-1)];
        float t = __powf(ws + EPSF, gamma);
        wpow[i] = t;
        lsum += t;
    }
    float psum = block_reduce_sum512(lsum, rbuf);
    float ip = 1.f / psum;
    #pragma unroll
    for (int i = 0; i < 4; i++) {
        float wv = wpow[i]*ip;
        woutb[tid + i*512] = wv;
        x[i] = wv;
    }
}

__device__ __forceinline__ void head_scalars(const float* __restrict__ p, float ksum, float* sc)
{
    sc[0] = sqrtf(ksum);
    sc[1] = softplusf(p[64]);
    sc[2] = sigmoidf(p[65]);
    float a0 = p[66], a1 = p[67], a2 = p[68];
    float mx = fmaxf(a0, fmaxf(a1, a2));
    float e0 = expf(a0-mx), e1 = expf(a1-mx), e2 = expf(a2-mx);
    float es = e0 + e1 + e2;
    sc[3] = e0/es; sc[4] = e1/es; sc[5] = e2/es;
    sc[6] = 1.f + softplusf(p[69]);
}

__device__ __forceinline__ void poly_x(
    float* x, const float* wdone, size_t base,
    float CC, float UU, float knorm, float beta)
{
    int tid = threadIdx.x;
    const size_t P = (size_t)B_*N_;
    const float* nrmp = g_norm + base;
    #pragma unroll
    for (int i = 0; i < 4; i++) {
        int n = tid + i*512;
        float w  = wdone[i];
        float Da = g_base[0*P + base + n];
        float Db = g_base[1*P + base + n];
        float S1 = g_base[2*P + base + n];
        float S2 = g_base[3*P + base + n];
        float T0 = g_base[4*P + base + n];
        float T1 = g_base[5*P + base + n];
        float nr = nrmp[n];
        float S0 = nr*nr;
        float dotv = Da - w*Db + w*CC;
        float w2 = w*w;
        float nsq = S0 - 2.f*w*S1 + w2*S2 + 2.f*w*T0 - 2.f*w2*T1 + w2*UU;
        float nn = sqrtf(fmaxf(nsq, 0.f));
        x[i] = beta * (dotv / (nn*knorm + EPSF));
    }
}

// ---------------- fused addressing: write heads 0&1 (y=0, longest first) + 4 read heads -------
__global__ void __launch_bounds__(512) address5_kernel(
    const float* __restrict__ prw,
    const float* __restrict__ pww,
    float* __restrict__ o_rw,
    float* __restrict__ o_ww)
{
    __shared__ float wg[2048];
    __shared__ float rbuf[32];
    __shared__ float sc[16];
    int b = blockIdx.x, hy = blockIdx.y, tid = threadIdx.x;
    size_t base = (size_t)b*N_;
    const size_t P = (size_t)B_*N_;

    if (hy != 0) {
        int h = hy - 1;   // read head 0..3
        const float* p = g_rp + ((size_t)h*B_ + b)*PR_;
        float kv = 0.f;
        if (tid < 64) { float xx = p[tid]; kv = xx*xx; }
        float ksum = block_reduce_sum512(kv, rbuf);
        if (tid == 0) head_scalars(p, ksum, sc);
        __syncthreads();
        float knorm = sc[0], beta = sc[1], g = sc[2];
        float s0 = sc[3], s1 = sc[4], s2 = sc[5], gamma = sc[6];

        const float* dotb = g_dot + (size_t)h*P + base;
        const float* nrmb = g_norm + base;
        float x[4];
        #pragma unroll
        for (int i = 0; i < 4; i++) {
            int n = tid + i*512;
            x[i] = beta * (dotb[n] / (nrmb[n]*knorm + EPSF));
        }
        address_tail(x, g, s0, s1, s2, gamma,
                     prw + (size_t)h*P + base, o_rw + (size_t)h*P + base, wg, rbuf);
    } else {
        const float* p0 = g_wp + (size_t)b*PW_;
        const float* p1 = g_wp + ((size_t)1*B_ + b)*PW_;
        float kv0 = 0.f, kv1 = 0.f, c1 = 0.f, c2 = 0.f;
        if (tid < 64) {
            float k0 = p0[tid], k1 = p1[tid];
            float a0 = tanhf(p0[134 + tid]);
            kv0 = k0*k0; kv1 = k1*k1; c1 = a0*k1; c2 = a0*a0;
        }
        float ks0 = block_reduce_sum512(kv0, rbuf);
        float ks1 = block_reduce_sum512(kv1, rbuf);
        float Cc  = block_reduce_sum512(c1, rbuf);
        float U   = block_reduce_sum512(c2, rbuf);
        if (tid == 0) {
            head_scalars(p0, ks0, sc);
            head_scalars(p1, ks1, sc + 7);
            sc[14] = Cc; sc[15] = U;
        }
        __syncthreads();

        float knorm = sc[0], beta = sc[1], g = sc[2];
        float s0 = sc[3], s1 = sc[4], s2 = sc[5], gamma = sc[6];
        const float* dotb = g_dot + 4*P + base;
        const float* nrmb = g_norm + base;
        float x[4];
        #pragma unroll
        for (int i = 0; i < 4; i++) {
            int n = tid + i*512;
            x[i] = beta * (dotb[n] / (nrmb[n]*knorm + EPSF));
        }
        address_tail(x, g, s0, s1, s2, gamma, pww + base, o_ww + base, wg, rbuf);
        __syncthreads();
        float y[4];
        poly_x(y, x, base, sc[14], sc[15], sc[7], sc[8]);
        address_tail(y, sc[9], sc[10], sc[11], sc[12], sc[13],
                     pww + P + base, o_ww + P + base, wg, rbuf);
    }
}

// ---------------- fused write heads 2 & 3 ----------------
__global__ void __launch_bounds__(512) addr23_kernel(
    const float* __restrict__ pww,
    float* __restrict__ o_ww)
{
    __shared__ float wg[2048];
    __shared__ float rbuf[32];
    __shared__ float sc[16];
    int b = blockIdx.x, tid = threadIdx.x;
    size_t base = (size_t)b*N_;
    const size_t P = (size_t)B_*N_;

    const float* p2 = g_wp + ((size_t)2*B_ + b)*PW_;
    const float* p3 = g_wp + ((size_t)3*B_ + b)*PW_;
    float kv2 = 0.f, kv3 = 0.f, c1 = 0.f, c2 = 0.f;
    if (tid < 64) {
        float k2 = p2[tid], k3 = p3[tid];
        float a2 = tanhf(p2[134 + tid]);
        kv2 = k2*k2; kv3 = k3*k3; c1 = a2*k3; c2 = a2*a2;
    }
    float ks2 = block_reduce_sum512(kv2, rbuf);
    float ks3 = block_reduce_sum512(kv3, rbuf);
    float Cc  = block_reduce_sum512(c1, rbuf);
    float U   = block_reduce_sum512(c2, rbuf);
    if (tid == 0) {
        head_scalars(p2, ks2, sc);
        head_scalars(p3, ks3, sc + 7);
        sc[14] = Cc; sc[15] = U;
    }
    __syncthreads();

    float knorm = sc[0], beta = sc[1], g = sc[2];
    float s0 = sc[3], s1 = sc[4], s2 = sc[5], gamma = sc[6];
    const float* dotb = g_dot + 4*P + base;
    const float* nrmb = g_norm + base;
    float x[4];
    #pragma unroll
    for (int i = 0; i < 4; i++) {
        int n = tid + i*512;
        x[i] = beta * (dotb[n] / (nrmb[n]*knorm + EPSF));
    }
    address_tail(x, g, s0, s1, s2, gamma, pww + 2*P + base, o_ww + 2*P + base, wg, rbuf);
    __syncthreads();
    float y[4];
    poly_x(y, x, base, sc[14], sc[15], sc[7], sc[8]);
    address_tail(y, sc[9], sc[10], sc[11], sc[12], sc[13],
                 pww + 3*P + base, o_ww + 3*P + base, wg, rbuf);
}

// ---------------- Sweep 1 (two-phase thread-per-row): stats + reads einsum ----------------
__global__ void __launch_bounds__(256) sweep1_kernel(
    const float* __restrict__ mem_in,
    const float* __restrict__ wr,
    const float* __restrict__ wwp,
    float* __restrict__ ro_part)
{
    int bc = blockIdx.x; int b = bc >> 3; int nb = (bc & 7) << 8;
    int tid = threadIdx.x, wid = tid >> 5, lane = tid & 31;
    const size_t P = (size_t)B_*N_;

    __shared__ float cst[11][64];
    __shared__ float ws4[256][4];
    __shared__ float2 sred[8][4][32];
    if (tid < 64) {
        const float* p0 = g_wp + (size_t)b*PW_;
        const float* p1 = g_wp + ((size_t)1*B_ + b)*PW_;
        const float* p2 = g_wp + ((size_t)2*B_ + b)*PW_;
        const float* p3 = g_wp + ((size_t)3*B_ + b)*PW_;
        float e2 = sigmoidf(p2[70 + tid]);
        float a2 = tanhf(p2[134 + tid]);
        float k3 = p3[tid];
        cst[0][tid]  = p2[tid];
        cst[1][tid]  = e2*k3;
        cst[2][tid]  = e2;
        cst[3][tid]  = e2*e2;
        cst[4][tid]  = a2;
        cst[5][tid]  = e2*a2;
        cst[6][tid]  = k3;
        cst[7][tid]  = sigmoidf(p0[70 + tid]);
        cst[8][tid]  = tanhf(p0[134 + tid]);
        cst[9][tid]  = sigmoidf(p1[70 + tid]);
        cst[10][tid] = tanhf(p1[134 + tid]);
    }
    size_t ix = (size_t)b*N_ + nb + tid;
    #pragma unroll
    for (int h = 0; h < 4; h++) ws4[tid][h] = wr[(size_t)h*P + ix];
    __syncthreads();

    // phase 1: per-row stats
    float w0 = wwp[ix], w1 = wwp[P + ix];
    const float4* rp4 = (const float4*)(mem_in + ix*M_);
    float acc[8] = {};
    #pragma unroll
    for (int mb = 0; mb < 16; mb++) {
        float4 d = rp4[mb];
        float4 c[11];
        #pragma unroll
        for (int ci = 0; ci < 11; ci++)
            c[ci] = *(const float4*)&cst[ci][mb*4];
        float vv[4] = {d.x, d.y, d.z, d.w};
        #pragma unroll
        for (int j = 0; j < 4; j++) {
            float v  = vv[j];
            float e0 = ((const float*)&c[7])[j], a0 = ((const float*)&c[8])[j];
            float e1 = ((const float*)&c[9])[j], a1 = ((const float*)&c[10])[j];
            float m1 = v*(1.f - w0*e0) + w0*a0;
            float m2 = m1*(1.f - w1*e1) + w1*a1;
            float s  = m2*m2;
            acc[0] += m2 * ((const float*)&c[0])[j];
            acc[1] += s;
            acc[2] += m2 * ((const float*)&c[6])[j];
            acc[3] += m2 * ((const float*)&c[1])[j];
            acc[4] += s  * ((const float*)&c[2])[j];
            acc[5] += s  * ((const float*)&c[3])[j];
            acc[6] += m2 * ((const float*)&c[4])[j];
            acc[7] += m2 * ((const float*)&c[5])[j];
        }
    }
    g_dot[4*P + ix] = acc[0];
    g_norm[ix] = sqrtf(acc[1]);
    #pragma unroll
    for (int r = 0; r < 6; r++) g_base[(size_t)r*P + ix] = acc[2+r];

    // phase 2: reads einsum (lane-per-m, L2-hot re-read)
    float2 racc[4] = {{0,0},{0,0},{0,0},{0,0}};
    size_t rowbase = (size_t)b*N_ + nb + wid*32;
    #pragma unroll 4
    for (int r = 0; r < 32; r++) {
        float2 v2 = *(const float2*)(mem_in + (rowbase + r)*M_ + 2*lane);
        float4 w4 = *(const float4*)&ws4[wid*32 + r][0];
        racc[0].x += w4.x*v2.x; racc[0].y += w4.x*v2.y;
        racc[1].x += w4.y*v2.x; racc[1].y += w4.y*v2.y;
        racc[2].x += w4.z*v2.x; racc[2].y += w4.z*v2.y;
        racc[3].x += w4.w*v2.x; racc[3].y += w4.w*v2.y;
    }
    #pragma unroll
    for (int h = 0; h < 4; h++) sred[wid][h][lane] = racc[h];
    __syncthreads();
    int h = tid >> 6, m = tid & 63;
    int l = m >> 1, c = m & 1;
    float s = 0.f;
    #pragma unroll
    for (int w = 0; w < 8; w++) {
        float2 t = sred[w][h][l];
        s += c ? t.y : t.x;
    }
    ro_part[(size_t)(bc & 7)*B_*256 + (size_t)b*256 + h*64 + m] = s;
}

// ---------------- Sweep 2: all 4 head updates, half-warp float4 (coalesced stores) ------------
__global__ void __launch_bounds__(256) sweep2_kernel(
    const float* __restrict__ mem_in, float* __restrict__ mem_out,
    const float* __restrict__ wwp)
{
    int bc = blockIdx.x; int b = bc >> 2; int nb = (bc & 3) << 9;
    int tid = threadIdx.x, wid = tid >> 5, lane = tid & 31;
    int hw = lane >> 4, l16 = lane & 15;

    float e[4][4], a[4][4];
    #pragma unroll
    for (int h = 0; h < 4; h++) {
        const float* ph = g_wp + ((size_t)h*B_ + b)*PW_;
        #pragma unroll
        for (int j = 0; j < 4; j++) {
            int m = l16*4 + j;
            e[h][j] = sigmoidf(ph[70 + m]);
            a[h][j] = tanhf(ph[134 + m]);
        }
    }

    const size_t P = (size_t)B_*N_;
    for (int it = 0; it < 32; it += 4) {
        int r0 = it*16 + wid*2 + hw;
        size_t ix[4];
        float4 v[4];
        #pragma unroll
        for (int q = 0; q < 4; q++) {
            ix[q] = (size_t)b*N_ + nb + r0 + q*16;
            v[q] = *(const float4*)(mem_in + ix[q]*M_ + l16*4);
        }
        float w[4][4];
        #pragma unroll
        for (int q = 0; q < 4; q++)
            #pragma unroll
            for (int h = 0; h < 4; h++)
                w[q][h] = wwp[(size_t)h*P + ix[q]];

        #pragma unroll
        for (int q = 0; q < 4; q++) {
            float vv[4] = {v[q].x, v[q].y, v[q].z, v[q].w};
            #pragma unroll
            for (int j = 0; j < 4; j++) {
                float m = vv[j];
                #pragma unroll
                for (int h = 0; h < 4; h++)
                    m = m*(1.f - w[q][h]*e[h][j]) + w[q][h]*a[h][j];
                vv[j] = m;
            }
            *(float4*)(mem_out + ix[q]*M_ + l16*4) = make_float4(vv[0], vv[1], vv[2], vv[3]);
        }
    }
}

// ---------------- host launcher ----------------
extern "C" void kernel_launch(void* const* d_in, const int* in_sizes, int n_in,
                              void* d_out, int out_size)
{
    const float* ext    = (const float*)d_in[0];
    const float* pread  = (const float*)d_in[1];
    const float* prw    = (const float*)d_in[2];
    const float* pww    = (const float*)d_in[3];
    const float* mem    = (const float*)d_in[4];
    const float* ctrlW  = (const float*)d_in[5];
    const float* ctrlb  = (const float*)d_in[6];
    const float* readW  = (const float*)d_in[7];
    const float* readb  = (const float*)d_in[8];
    const float* writeW = (const float*)d_in[9];
    const float* writeb = (const float*)d_in[10];
    const float* outW   = (const float*)d_in[11];
    const float* outb   = (const float*)d_in[12];
    float* out = (float*)d_out;

    float *ctrl, *rp, *wp, *ropart;
    cudaGetSymbolAddress((void**)&ctrl,   g_ctrl);
    cudaGetSymbolAddress((void**)&rp,     g_rp);
    cudaGetSymbolAddress((void**)&wp,     g_wp);
    cudaGetSymbolAddress((void**)&ropart, g_ropart);

    float* o_mem = out + OUT_MEM;
    float* o_ro  = out + OUT_RO;
    float* o_rw  = out + OUT_RW;
    float* o_ww  = out + OUT_WW;

    // Side stream + events for overlapping the output GEMM with addr23/sweep2.
    // Created once; event fork/join keeps graph capture legal.
    static cudaStream_t s2 = nullptr;
    static cudaEvent_t evFork = nullptr, evJoin = nullptr;
    if (s2 == nullptr) {
        cudaStreamCreateWithFlags(&s2, cudaStreamNonBlocking);
        cudaEventCreateWithFlags(&evFork, cudaEventDisableTiming);
        cudaEventCreateWithFlags(&evJoin, cudaEventDisableTiming);
    }

    // Controller GEMM with fused concat
    gemm_cat_kernel<<<dim3(8, 8), 256>>>(ext, 256, pread, 256, ctrlW, ctrlb, ctrl, 512);

    // All 8 head parameter GEMMs in one launch
    gemm_heads_kernel<<<dim3(4, 8, 8), 256>>>(ctrl, readW, readb, rp, writeW, writeb, wp);

    // Pass A (thread-per-row)
    passA_kernel<<<2048, 256>>>(mem);

    // Addressing: write heads 0&1 (y=0, scheduled first) + 4 read heads
    address5_kernel<<<dim3(256, 5), 512>>>(prw, pww, o_rw, o_ww);

    // Sweep 1: stats (thread-per-row) + reads einsum (lane-per-m)
    sweep1_kernel<<<2048, 256>>>(mem, o_rw, o_ww, ropart);

    // Fork: output GEMM (depends only on sweep1's ro_part) runs on side stream,
    // concurrent with addr23 + sweep2 on the main stream.
    cudaEventRecord(evFork, 0);
    cudaStreamWaitEvent(s2, evFork, 0);
    gemm_out_kernel<<<dim3(4, 8), 256, 0, s2>>>(ctrl, ropart, outW, outb, out, o_ro);
    cudaEventRecord(evJoin, s2);

    // Write heads 2 & 3, then final memory sweep
    addr23_kernel<<<256, 512>>>(pww, o_ww);
    sweep2_kernel<<<1024, 256>>>(mem, o_mem, o_ww);

    // Join side stream back
    cudaStreamWaitEvent(0, evJoin, 0);
}

// round 16
// speedup vs baseline: 1.2790x; 1.0323x over previous
#include <cuda_runtime.h>
#include <math.h>

// Problem constants
constexpr int B_  = 256;
constexpr int N_  = 2048;
constexpr int M_  = 64;
constexpr int C_  = 512;
constexpr int PR_ = 70;   // M + 3 + SHIFT
constexpr int PW_ = 198;  // PR + 2M
constexpr float EPSF = 1e-8f;

// Output layout (floats): ntm_out, memory, read_out, new_read_w, new_write_w
constexpr size_t OUT_MEM = 65536;
constexpr size_t OUT_RO  = 33619968;
constexpr size_t OUT_RW  = 33685504;
constexpr size_t OUT_WW  = 35782656;

// ---------------- device scratch ----------------
__device__ float g_ctrl[B_*C_];
__device__ float g_rp  [4*B_*PR_];
__device__ float g_wp  [4*B_*PW_];
__device__ float g_dot [5*(size_t)B_*N_];
__device__ float g_norm[(size_t)B_*N_];
__device__ float g_base[6*(size_t)B_*N_];   // base dots: Da,Db,S1,S2,T0,T1
__device__ float g_ropart[8*B_*256];

__device__ __forceinline__ float softplusf(float x){ return x > 20.f ? x : log1pf(expf(x)); }
__device__ __forceinline__ float sigmoidf (float x){ return 1.f/(1.f+expf(-x)); }

// ---------------- GEMM body (proven): tile 32x64, K-step 32, 256 threads ----------------
__device__ __forceinline__ void gemm_body(
    const float* __restrict__ A0, int ca,
    const float* __restrict__ A1, int cb,
    const float* __restrict__ W, const float* __restrict__ bias,
    float* __restrict__ out, int Nc)
{
    int col0 = blockIdx.x * 64;
    if (col0 >= Nc) return;
    int row0 = blockIdx.y * 32;
    int K = ca + cb;

    __shared__ float As[32][33];
    __shared__ float Ws[32][64];
    int tid = threadIdx.x;
    int tx = tid & 15, ty = tid >> 4;
    float acc[2][4] = {};

    for (int k0 = 0; k0 < K; k0 += 32) {
        {
            int m  = tid >> 3;
            int kk = (tid & 7) * 4;
            int r = row0 + m, c = k0 + kk;
            float4 v;
            if (c < ca) v = *(const float4*)(A0 + (size_t)r*ca + c);
            else        v = *(const float4*)(A1 + (size_t)r*cb + (c - ca));
            As[m][kk] = v.x; As[m][kk+1] = v.y; As[m][kk+2] = v.z; As[m][kk+3] = v.w;
        }
        {
            int kk = tid >> 3;
            int n0 = (tid & 7) * 8;
            const float* wrow = W + (size_t)(k0 + kk)*Nc + col0 + n0;
            #pragma unroll
            for (int j = 0; j < 8; j++) {
                int gn = col0 + n0 + j;
                Ws[kk][n0 + j] = (gn < Nc) ? wrow[j] : 0.f;
            }
        }
        __syncthreads();
        #pragma unroll
        for (int kk = 0; kk < 32; kk++) {
            float a0 = As[ty*2 + 0][kk];
            float a1 = As[ty*2 + 1][kk];
            float4 w4 = *(const float4*)&Ws[kk][tx*4];
            acc[0][0] += a0*w4.x; acc[0][1] += a0*w4.y; acc[0][2] += a0*w4.z; acc[0][3] += a0*w4.w;
            acc[1][0] += a1*w4.x; acc[1][1] += a1*w4.y; acc[1][2] += a1*w4.z; acc[1][3] += a1*w4.w;
        }
        __syncthreads();
    }
    #pragma unroll
    for (int i = 0; i < 2; i++) {
        int gm = row0 + ty*2 + i;
        #pragma unroll
        for (int j = 0; j < 4; j++) {
            int gn = col0 + tx*4 + j;
            if (gn < Nc) out[(size_t)gm*Nc + gn] = acc[i][j] + bias[gn];
        }
    }
}

__global__ void gemm_cat_kernel(const float* __restrict__ A0, int ca,
                                const float* __restrict__ A1, int cb,
                                const float* __restrict__ W, const float* __restrict__ bias,
                                float* __restrict__ out, int Nc)
{
    gemm_body(A0, ca, A1, cb, W, bias, out, Nc);
}

__global__ void gemm_heads_kernel(const float* __restrict__ ctrl,
                                  const float* __restrict__ readW, const float* __restrict__ readb,
                                  float* __restrict__ rp,
                                  const float* __restrict__ writeW, const float* __restrict__ writeb,
                                  float* __restrict__ wp)
{
    int h = blockIdx.z;
    const float *W, *bias; float* out; int Nc;
    if (h < 4) {
        W = readW + (size_t)h*C_*PR_; bias = readb + h*PR_;
        out = rp + (size_t)h*B_*PR_;  Nc = PR_;
    } else {
        int g = h - 4;
        W = writeW + (size_t)g*C_*PW_; bias = writeb + g*PW_;
        out = wp + (size_t)g*B_*PW_;   Nc = PW_;
    }
    gemm_body(ctrl, C_, nullptr, 0, W, bias, out, Nc);
}

// ---------------- Output GEMM half (rows rb0..rb0+127) with fused ro-sum ----------------
__global__ void __launch_bounds__(256) gemm_out_kernel(
    int rb0,
    const float* __restrict__ ctrl, const float* __restrict__ part,
    const float* __restrict__ W, const float* __restrict__ bias,
    float* __restrict__ out, float* __restrict__ o_ro)
{
    __shared__ float As[32][33];
    __shared__ float Ws[32][64];
    constexpr int Nc = 256;
    int tid = threadIdx.x;
    int cx = blockIdx.x;
    int col0 = cx * 64;
    int row0 = rb0 + blockIdx.y * 32;
    int tx = tid & 15, ty = tid >> 4;
    float acc[2][4] = {};

    for (int k0 = 0; k0 < 768; k0 += 32) {
        {
            int m  = tid >> 3;
            int kk = (tid & 7) * 4;
            int r = row0 + m, c = k0 + kk;
            float4 v;
            if (c < 512) {
                v = *(const float4*)(ctrl + (size_t)r*512 + c);
            } else {
                int cc = c - 512;
                const float* p = part + (size_t)r*256 + cc;
                v = *(const float4*)p;
                #pragma unroll
                for (int q = 1; q < 8; q++) {
                    float4 vq = *(const float4*)(p + (size_t)q*B_*256);
                    v.x += vq.x; v.y += vq.y; v.z += vq.z; v.w += vq.w;
                }
                if (cx == 0)
                    *(float4*)(o_ro + (size_t)r*256 + cc) = v;
            }
            As[m][kk] = v.x; As[m][kk+1] = v.y; As[m][kk+2] = v.z; As[m][kk+3] = v.w;
        }
        {
            int kk = tid >> 3;
            int n0 = (tid & 7) * 8;
            const float* wrow = W + (size_t)(k0 + kk)*Nc + col0 + n0;
            #pragma unroll
            for (int j = 0; j < 8; j++)
                Ws[kk][n0 + j] = wrow[j];
        }
        __syncthreads();
        #pragma unroll
        for (int kk = 0; kk < 32; kk++) {
            float a0 = As[ty*2 + 0][kk];
            float a1 = As[ty*2 + 1][kk];
            float4 w4 = *(const float4*)&Ws[kk][tx*4];
            acc[0][0] += a0*w4.x; acc[0][1] += a0*w4.y; acc[0][2] += a0*w4.z; acc[0][3] += a0*w4.w;
            acc[1][0] += a1*w4.x; acc[1][1] += a1*w4.y; acc[1][2] += a1*w4.z; acc[1][3] += a1*w4.w;
        }
        __syncthreads();
    }
    #pragma unroll
    for (int i = 0; i < 2; i++) {
        int gm = row0 + ty*2 + i;
        #pragma unroll
        for (int j = 0; j < 4; j++) {
            int gn = col0 + tx*4 + j;
            out[(size_t)gm*Nc + gn] = acc[i][j] + bias[gn];
        }
    }
}

// ---------------- Pass A (half): thread-per-row, smem constants ----------------
__global__ void __launch_bounds__(256) passA_kernel(const float* __restrict__ mem, int b0)
{
    int bc = blockIdx.x; int b = b0 + (bc >> 3); int nb = (bc & 7) << 8;
    int tid = threadIdx.x;

    __shared__ float cst[11][64];
    for (int i = tid; i < 5*64; i += 256) {
        int h = i >> 6, m = i & 63;
        cst[h][m] = (h < 4) ? g_rp[((size_t)h*B_ + b)*PR_ + m]
                            : g_wp[(size_t)b*PW_ + m];
    }
    if (tid < 64) {
        const float* wp0 = g_wp + (size_t)b*PW_;
        const float* wp1 = g_wp + ((size_t)B_ + b)*PW_;
        float e0 = sigmoidf(wp0[70 + tid]);
        float a0 = tanhf(wp0[134 + tid]);
        float k1 = wp1[tid];
        cst[5][tid]  = k1;
        cst[6][tid]  = e0*k1;
        cst[7][tid]  = e0;
        cst[8][tid]  = e0*e0;
        cst[9][tid]  = a0;
        cst[10][tid] = e0*a0;
    }
    __syncthreads();

    size_t ix = (size_t)b*N_ + nb + tid;
    const float4* rp4 = (const float4*)(mem + ix*M_);

    float acc[12] = {};
    #pragma unroll
    for (int mb = 0; mb < 16; mb++) {
        float4 d = rp4[mb];
        float4 c[11];
        #pragma unroll
        for (int ci = 0; ci < 11; ci++)
            c[ci] = *(const float4*)&cst[ci][mb*4];
        float vv[4] = {d.x, d.y, d.z, d.w};
        #pragma unroll
        for (int j = 0; j < 4; j++) {
            float v  = vv[j];
            float vs = v*v;
            acc[0]  += vs;
            acc[1]  += v * ((const float*)&c[0])[j];
            acc[2]  += v * ((const float*)&c[1])[j];
            acc[3]  += v * ((const float*)&c[2])[j];
            acc[4]  += v * ((const float*)&c[3])[j];
            acc[5]  += v * ((const float*)&c[4])[j];
            acc[6]  += v * ((const float*)&c[5])[j];
            acc[7]  += v * ((const float*)&c[6])[j];
            acc[8]  += vs * ((const float*)&c[7])[j];
            acc[9]  += vs * ((const float*)&c[8])[j];
            acc[10] += v * ((const float*)&c[9])[j];
            acc[11] += v * ((const float*)&c[10])[j];
        }
    }

    const size_t P = (size_t)B_*N_;
    g_norm[ix] = sqrtf(acc[0]);
    #pragma unroll
    for (int h = 0; h < 5; h++) g_dot[(size_t)h*P + ix] = acc[1+h];
    #pragma unroll
    for (int r = 0; r < 6; r++) g_base[(size_t)r*P + ix] = acc[6+r];
}

// ---------------- block reduction helpers (512 threads) ----------------
__device__ __forceinline__ float block_reduce_sum512(float v, float* sbuf)
{
    int tid = threadIdx.x;
    #pragma unroll
    for (int o = 16; o > 0; o >>= 1) v += __shfl_xor_sync(0xffffffffu, v, o);
    if ((tid & 31) == 0) sbuf[tid >> 5] = v;
    __syncthreads();
    if (tid < 32) {
        float x = (tid < 16) ? sbuf[tid] : 0.f;
        #pragma unroll
        for (int o = 8; o > 0; o >>= 1) x += __shfl_xor_sync(0xffffffffu, x, o);
        if (tid == 0) sbuf[0] = x;
    }
    __syncthreads();
    float r = sbuf[0];
    __syncthreads();
    return r;
}

__device__ __forceinline__ float block_reduce_max512(float v, float* sbuf)
{
    int tid = threadIdx.x;
    #pragma unroll
    for (int o = 16; o > 0; o >>= 1) v = fmaxf(v, __shfl_xor_sync(0xffffffffu, v, o));
    if ((tid & 31) == 0) sbuf[tid >> 5] = v;
    __syncthreads();
    if (tid < 32) {
        float x = (tid < 16) ? sbuf[tid] : -3.4e38f;
        #pragma unroll
        for (int o = 8; o > 0; o >>= 1) x = fmaxf(x, __shfl_xor_sync(0xffffffffu, x, o));
        if (tid == 0) sbuf[0] = x;
    }
    __syncthreads();
    float r = sbuf[0];
    __syncthreads();
    return r;
}

// ---------------- addressing tail (512 threads, 4 items/thread) ----------------
__device__ __forceinline__ void address_tail(
    float* x, float g, float s0, float s1, float s2, float gamma,
    const float* __restrict__ wpb, float* __restrict__ woutb,
    float* wg, float* rbuf)
{
    int tid = threadIdx.x;
    float mx = fmaxf(fmaxf(x[0], x[1]), fmaxf(x[2], x[3]));
    float bmax = block_reduce_max512(mx, rbuf);
    float lsum = 0.f;
    #pragma unroll
    for (int i = 0; i < 4; i++) {
        float e = __expf(x[i] - bmax);
        wg[tid + i*512] = e;
        lsum += e;
    }
    float bsum = block_reduce_sum512(lsum, rbuf);
    float inv = 1.f / bsum;
    #pragma unroll
    for (int i = 0; i < 4; i++) {
        int n = tid + i*512;
        wg[n] = g * (wg[n]*inv) + (1.f-g) * wpb[n];
    }
    __syncthreads();
    float wpow[4];
    lsum = 0.f;
    #pragma unroll
    for (int i = 0; i < 4; i++) {
        int n = tid + i*512;
        float ws = s0*wg[(n+1)&(N_-1)] + s1*wg[n] + s2*wg[(n-1)&(N_-1)];
        float t = __powf(ws + EPSF, gamma);
        wpow[i] = t;
        lsum += t;
    }
    float psum = block_reduce_sum512(lsum, rbuf);
    float ip = 1.f / psum;
    #pragma unroll
    for (int i = 0; i < 4; i++) {
        float wv = wpow[i]*ip;
        woutb[tid + i*512] = wv;
        x[i] = wv;
    }
}

__device__ __forceinline__ void head_scalars(const float* __restrict__ p, float ksum, float* sc)
{
    sc[0] = sqrtf(ksum);
    sc[1] = softplusf(p[64]);
    sc[2] = sigmoidf(p[65]);
    float a0 = p[66], a1 = p[67], a2 = p[68];
    float mx = fmaxf(a0, fmaxf(a1, a2));
    float e0 = expf(a0-mx), e1 = expf(a1-mx), e2 = expf(a2-mx);
    float es = e0 + e1 + e2;
    sc[3] = e0/es; sc[4] = e1/es; sc[5] = e2/es;
    sc[6] = 1.f + softplusf(p[69]);
}

__device__ __forceinline__ void poly_x(
    float* x, const float* wdone, size_t base,
    float CC, float UU, float knorm, float beta)
{
    int tid = threadIdx.x;
    const size_t P = (size_t)B_*N_;
    const float* nrmp = g_norm + base;
    #pragma unroll
    for (int i = 0; i < 4; i++) {
        int n = tid + i*512;
        float w  = wdone[i];
        float Da = g_base[0*P + base + n];
        float Db = g_base[1*P + base + n];
        float S1 = g_base[2*P + base + n];
        float S2 = g_base[3*P + base + n];
        float T0 = g_base[4*P + base + n];
        float T1 = g_base[5*P + base + n];
        float nr = nrmp[n];
        float S0 = nr*nr;
        float dotv = Da - w*Db + w*CC;
        float w2 = w*w;
        float nsq = S0 - 2.f*w*S1 + w2*S2 + 2.f*w*T0 - 2.f*w2*T1 + w2*UU;
        float nn = sqrtf(fmaxf(nsq, 0.f));
        x[i] = beta * (dotv / (nn*knorm + EPSF));
    }
}

// ---------------- fused addressing (half): write heads 0&1 (y=0) + 4 read heads ----------------
__global__ void __launch_bounds__(512) address5_kernel(
    int b0,
    const float* __restrict__ prw,
    const float* __restrict__ pww,
    float* __restrict__ o_rw,
    float* __restrict__ o_ww)
{
    __shared__ float wg[2048];
    __shared__ float rbuf[32];
    __shared__ float sc[16];
    int b = b0 + blockIdx.x, hy = blockIdx.y, tid = threadIdx.x;
    size_t base = (size_t)b*N_;
    const size_t P = (size_t)B_*N_;

    if (hy != 0) {
        int h = hy - 1;
        const float* p = g_rp + ((size_t)h*B_ + b)*PR_;
        float kv = 0.f;
        if (tid < 64) { float xx = p[tid]; kv = xx*xx; }
        float ksum = block_reduce_sum512(kv, rbuf);
        if (tid == 0) head_scalars(p, ksum, sc);
        __syncthreads();
        float knorm = sc[0], beta = sc[1], g = sc[2];
        float s0 = sc[3], s1 = sc[4], s2 = sc[5], gamma = sc[6];

        const float* dotb = g_dot + (size_t)h*P + base;
        const float* nrmb = g_norm + base;
        float x[4];
        #pragma unroll
        for (int i = 0; i < 4; i++) {
            int n = tid + i*512;
            x[i] = beta * (dotb[n] / (nrmb[n]*knorm + EPSF));
        }
        address_tail(x, g, s0, s1, s2, gamma,
                     prw + (size_t)h*P + base, o_rw + (size_t)h*P + base, wg, rbuf);
    } else {
        const float* p0 = g_wp + (size_t)b*PW_;
        const float* p1 = g_wp + ((size_t)1*B_ + b)*PW_;
        float kv0 = 0.f, kv1 = 0.f, c1 = 0.f, c2 = 0.f;
        if (tid < 64) {
            float k0 = p0[tid], k1 = p1[tid];
            float a0 = tanhf(p0[134 + tid]);
            kv0 = k0*k0; kv1 = k1*k1; c1 = a0*k1; c2 = a0*a0;
        }
        float ks0 = block_reduce_sum512(kv0, rbuf);
        float ks1 = block_reduce_sum512(kv1, rbuf);
        float Cc  = block_reduce_sum512(c1, rbuf);
        float U   = block_reduce_sum512(c2, rbuf);
        if (tid == 0) {
            head_scalars(p0, ks0, sc);
            head_scalars(p1, ks1, sc + 7);
            sc[14] = Cc; sc[15] = U;
        }
        __syncthreads();

        float knorm = sc[0], beta = sc[1], g = sc[2];
        float s0 = sc[3], s1 = sc[4], s2 = sc[5], gamma = sc[6];
        const float* dotb = g_dot + 4*P + base;
        const float* nrmb = g_norm + base;
        float x[4];
        #pragma unroll
        for (int i = 0; i < 4; i++) {
            int n = tid + i*512;
            x[i] = beta * (dotb[n] / (nrmb[n]*knorm + EPSF));
        }
        address_tail(x, g, s0, s1, s2, gamma, pww + base, o_ww + base, wg, rbuf);
        __syncthreads();
        float y[4];
        poly_x(y, x, base, sc[14], sc[15], sc[7], sc[8]);
        address_tail(y, sc[9], sc[10], sc[11], sc[12], sc[13],
                     pww + P + base, o_ww + P + base, wg, rbuf);
    }
}

// ---------------- fused write heads 2 & 3 (half) ----------------
__global__ void __launch_bounds__(512) addr23_kernel(
    int b0,
    const float* __restrict__ pww,
    float* __restrict__ o_ww)
{
    __shared__ float wg[2048];
    __shared__ float rbuf[32];
    __shared__ float sc[16];
    int b = b0 + blockIdx.x, tid = threadIdx.x;
    size_t base = (size_t)b*N_;
    const size_t P = (size_t)B_*N_;

    const float* p2 = g_wp + ((size_t)2*B_ + b)*PW_;
    const float* p3 = g_wp + ((size_t)3*B_ + b)*PW_;
    float kv2 = 0.f, kv3 = 0.f, c1 = 0.f, c2 = 0.f;
    if (tid < 64) {
        float k2 = p2[tid], k3 = p3[tid];
        float a2 = tanhf(p2[134 + tid]);
        kv2 = k2*k2; kv3 = k3*k3; c1 = a2*k3; c2 = a2*a2;
    }
    float ks2 = block_reduce_sum512(kv2, rbuf);
    float ks3 = block_reduce_sum512(kv3, rbuf);
    float Cc  = block_reduce_sum512(c1, rbuf);
    float U   = block_reduce_sum512(c2, rbuf);
    if (tid == 0) {
        head_scalars(p2, ks2, sc);
        head_scalars(p3, ks3, sc + 7);
        sc[14] = Cc; sc[15] = U;
    }
    __syncthreads();

    float knorm = sc[0], beta = sc[1], g = sc[2];
    float s0 = sc[3], s1 = sc[4], s2 = sc[5], gamma = sc[6];
    const float* dotb = g_dot + 4*P + base;
    const float* nrmb = g_norm + base;
    float x[4];
    #pragma unroll
    for (int i = 0; i < 4; i++) {
        int n = tid + i*512;
        x[i] = beta * (dotb[n] / (nrmb[n]*knorm + EPSF));
    }
    address_tail(x, g, s0, s1, s2, gamma, pww + 2*P + base, o_ww + 2*P + base, wg, rbuf);
    __syncthreads();
    float y[4];
    poly_x(y, x, base, sc[14], sc[15], sc[7], sc[8]);
    address_tail(y, sc[9], sc[10], sc[11], sc[12], sc[13],
                 pww + 3*P + base, o_ww + 3*P + base, wg, rbuf);
}

// ---------------- Sweep 1 (half, two-phase thread-per-row): stats + reads einsum --------------
__global__ void __launch_bounds__(256) sweep1_kernel(
    int b0,
    const float* __restrict__ mem_in,
    const float* __restrict__ wr,
    const float* __restrict__ wwp,
    float* __restrict__ ro_part)
{
    int bc = blockIdx.x; int b = b0 + (bc >> 3); int nb = (bc & 7) << 8;
    int tid = threadIdx.x, wid = tid >> 5, lane = tid & 31;
    const size_t P = (size_t)B_*N_;

    __shared__ float cst[11][64];
    __shared__ float ws4[256][4];
    __shared__ float2 sred[8][4][32];
    if (tid < 64) {
        const float* p0 = g_wp + (size_t)b*PW_;
        const float* p1 = g_wp + ((size_t)1*B_ + b)*PW_;
        const float* p2 = g_wp + ((size_t)2*B_ + b)*PW_;
        const float* p3 = g_wp + ((size_t)3*B_ + b)*PW_;
        float e2 = sigmoidf(p2[70 + tid]);
        float a2 = tanhf(p2[134 + tid]);
        float k3 = p3[tid];
        cst[0][tid]  = p2[tid];
        cst[1][tid]  = e2*k3;
        cst[2][tid]  = e2;
        cst[3][tid]  = e2*e2;
        cst[4][tid]  = a2;
        cst[5][tid]  = e2*a2;
        cst[6][tid]  = k3;
        cst[7][tid]  = sigmoidf(p0[70 + tid]);
        cst[8][tid]  = tanhf(p0[134 + tid]);
        cst[9][tid]  = sigmoidf(p1[70 + tid]);
        cst[10][tid] = tanhf(p1[134 + tid]);
    }
    size_t ix = (size_t)b*N_ + nb + tid;
    #pragma unroll
    for (int h = 0; h < 4; h++) ws4[tid][h] = wr[(size_t)h*P + ix];
    __syncthreads();

    // phase 1: per-row stats
    float w0 = wwp[ix], w1 = wwp[P + ix];
    const float4* rp4 = (const float4*)(mem_in + ix*M_);
    float acc[8] = {};
    #pragma unroll
    for (int mb = 0; mb < 16; mb++) {
        float4 d = rp4[mb];
        float4 c[11];
        #pragma unroll
        for (int ci = 0; ci < 11; ci++)
            c[ci] = *(const float4*)&cst[ci][mb*4];
        float vv[4] = {d.x, d.y, d.z, d.w};
        #pragma unroll
        for (int j = 0; j < 4; j++) {
            float v  = vv[j];
            float e0 = ((const float*)&c[7])[j], a0 = ((const float*)&c[8])[j];
            float e1 = ((const float*)&c[9])[j], a1 = ((const float*)&c[10])[j];
            float m1 = v*(1.f - w0*e0) + w0*a0;
            float m2 = m1*(1.f - w1*e1) + w1*a1;
            float s  = m2*m2;
            acc[0] += m2 * ((const float*)&c[0])[j];
            acc[1] += s;
            acc[2] += m2 * ((const float*)&c[6])[j];
            acc[3] += m2 * ((const float*)&c[1])[j];
            acc[4] += s  * ((const float*)&c[2])[j];
            acc[5] += s  * ((const float*)&c[3])[j];
            acc[6] += m2 * ((const float*)&c[4])[j];
            acc[7] += m2 * ((const float*)&c[5])[j];
        }
    }
    g_dot[4*P + ix] = acc[0];
    g_norm[ix] = sqrtf(acc[1]);
    #pragma unroll
    for (int r = 0; r < 6; r++) g_base[(size_t)r*P + ix] = acc[2+r];

    // phase 2: reads einsum (lane-per-m, L1/L2-hot re-read)
    float2 racc[4] = {{0,0},{0,0},{0,0},{0,0}};
    size_t rowbase = (size_t)b*N_ + nb + wid*32;
    #pragma unroll 4
    for (int r = 0; r < 32; r++) {
        float2 v2 = *(const float2*)(mem_in + (rowbase + r)*M_ + 2*lane);
        float4 w4 = *(const float4*)&ws4[wid*32 + r][0];
        racc[0].x += w4.x*v2.x; racc[0].y += w4.x*v2.y;
        racc[1].x += w4.y*v2.x; racc[1].y += w4.y*v2.y;
        racc[2].x += w4.z*v2.x; racc[2].y += w4.z*v2.y;
        racc[3].x += w4.w*v2.x; racc[3].y += w4.w*v2.y;
    }
    #pragma unroll
    for (int h = 0; h < 4; h++) sred[wid][h][lane] = racc[h];
    __syncthreads();
    int h = tid >> 6, m = tid & 63;
    int l = m >> 1, c = m & 1;
    float s = 0.f;
    #pragma unroll
    for (int w = 0; w < 8; w++) {
        float2 t = sred[w][h][l];
        s += c ? t.y : t.x;
    }
    ro_part[(size_t)(bc & 7)*B_*256 + (size_t)b*256 + h*64 + m] = s;
}

// ---------------- Sweep 2 (half): all 4 head updates, half-warp float4 ----------------
__global__ void __launch_bounds__(256) sweep2_kernel(
    int b0,
    const float* __restrict__ mem_in, float* __restrict__ mem_out,
    const float* __restrict__ wwp)
{
    int bc = blockIdx.x; int b = b0 + (bc >> 2); int nb = (bc & 3) << 9;
    int tid = threadIdx.x, wid = tid >> 5, lane = tid & 31;
    int hw = lane >> 4, l16 = lane & 15;

    float e[4][4], a[4][4];
    #pragma unroll
    for (int h = 0; h < 4; h++) {
        const float* ph = g_wp + ((size_t)h*B_ + b)*PW_;
        #pragma unroll
        for (int j = 0; j < 4; j++) {
            int m = l16*4 + j;
            e[h][j] = sigmoidf(ph[70 + m]);
            a[h][j] = tanhf(ph[134 + m]);
        }
    }

    const size_t P = (size_t)B_*N_;
    for (int it = 0; it < 32; it += 4) {
        int r0 = it*16 + wid*2 + hw;
        size_t ix[4];
        float4 v[4];
        #pragma unroll
        for (int q = 0; q < 4; q++) {
            ix[q] = (size_t)b*N_ + nb + r0 + q*16;
            v[q] = *(const float4*)(mem_in + ix[q]*M_ + l16*4);
        }
        float w[4][4];
        #pragma unroll
        for (int q = 0; q < 4; q++)
            #pragma unroll
            for (int h = 0; h < 4; h++)
                w[q][h] = wwp[(size_t)h*P + ix[q]];

        #pragma unroll
        for (int q = 0; q < 4; q++) {
            float vv[4] = {v[q].x, v[q].y, v[q].z, v[q].w};
            #pragma unroll
            for (int j = 0; j < 4; j++) {
                float m = vv[j];
                #pragma unroll
                for (int h = 0; h < 4; h++)
                    m = m*(1.f - w[q][h]*e[h][j]) + w[q][h]*a[h][j];
                vv[j] = m;
            }
            *(float4*)(mem_out + ix[q]*M_ + l16*4) = make_float4(vv[0], vv[1], vv[2], vv[3]);
        }
    }
}

// ---------------- host launcher ----------------
extern "C" void kernel_launch(void* const* d_in, const int* in_sizes, int n_in,
                              void* d_out, int out_size)
{
    const float* ext    = (const float*)d_in[0];
    const float* pread  = (const float*)d_in[1];
    const float* prw    = (const float*)d_in[2];
    const float* pww    = (const float*)d_in[3];
    const float* mem    = (const float*)d_in[4];
    const float* ctrlW  = (const float*)d_in[5];
    const float* ctrlb  = (const float*)d_in[6];
    const float* readW  = (const float*)d_in[7];
    const float* readb  = (const float*)d_in[8];
    const float* writeW = (const float*)d_in[9];
    const float* writeb = (const float*)d_in[10];
    const float* outW   = (const float*)d_in[11];
    const float* outb   = (const float*)d_in[12];
    float* out = (float*)d_out;

    float *ctrl, *rp, *wp, *ropart;
    cudaGetSymbolAddress((void**)&ctrl,   g_ctrl);
    cudaGetSymbolAddress((void**)&rp,     g_rp);
    cudaGetSymbolAddress((void**)&wp,     g_wp);
    cudaGetSymbolAddress((void**)&ropart, g_ropart);

    float* o_mem = out + OUT_MEM;
    float* o_ro  = out + OUT_RO;
    float* o_rw  = out + OUT_RW;
    float* o_ww  = out + OUT_WW;

    // Streams/events (created once on the uncaptured correctness call).
    static cudaStream_t s2 = nullptr, s3 = nullptr, s4 = nullptr;
    static cudaEvent_t evFork = nullptr, evA = nullptr, evB = nullptr;
    static cudaEvent_t evJA = nullptr, evJB = nullptr, evJ2 = nullptr;
    if (s2 == nullptr) {
        cudaStreamCreateWithFlags(&s2, cudaStreamNonBlocking);
        cudaStreamCreateWithFlags(&s3, cudaStreamNonBlocking);
        cudaStreamCreateWithFlags(&s4, cudaStreamNonBlocking);
        cudaEventCreateWithFlags(&evFork, cudaEventDisableTiming);
        cudaEventCreateWithFlags(&evA, cudaEventDisableTiming);
        cudaEventCreateWithFlags(&evB, cudaEventDisableTiming);
        cudaEventCreateWithFlags(&evJA, cudaEventDisableTiming);
        cudaEventCreateWithFlags(&evJB, cudaEventDisableTiming);
        cudaEventCreateWithFlags(&evJ2, cudaEventDisableTiming);
    }

    // Shared prologue on main stream
    gemm_cat_kernel<<<dim3(8, 8), 256>>>(ext, 256, pread, 256, ctrlW, ctrlb, ctrl, 512);
    gemm_heads_kernel<<<dim3(4, 8, 8), 256>>>(ctrl, readW, readb, rp, writeW, writeb, wp);

    // Fork batch-half 1 onto s2
    cudaEventRecord(evFork, 0);
    cudaStreamWaitEvent(s2, evFork, 0);

    // Half 0 (b 0..127) on main stream; half 1 (b 128..255) on s2 — interleaved launches
    passA_kernel<<<1024, 256, 0, 0 >>>(mem, 0);
    passA_kernel<<<1024, 256, 0, s2>>>(mem, 128);

    address5_kernel<<<dim3(128, 5), 512, 0, 0 >>>(0,   prw, pww, o_rw, o_ww);
    address5_kernel<<<dim3(128, 5), 512, 0, s2>>>(128, prw, pww, o_rw, o_ww);

    sweep1_kernel<<<1024, 256, 0, 0 >>>(0,   mem, o_rw, o_ww, ropart);
    sweep1_kernel<<<1024, 256, 0, s2>>>(128, mem, o_rw, o_ww, ropart);

    // Out-GEMM halves fork off each half's sweep1 (rows == b)
    cudaEventRecord(evA, 0);
    cudaStreamWaitEvent(s3, evA, 0);
    gemm_out_kernel<<<dim3(4, 4), 256, 0, s3>>>(0,   ctrl, ropart, outW, outb, out, o_ro);
    cudaEventRecord(evJA, s3);

    cudaEventRecord(evB, s2);
    cudaStreamWaitEvent(s4, evB, 0);
    gemm_out_kernel<<<dim3(4, 4), 256, 0, s4>>>(128, ctrl, ropart, outW, outb, out, o_ro);
    cudaEventRecord(evJB, s4);

    // Write heads 2&3 + final sweep per half
    addr23_kernel<<<128, 512, 0, 0 >>>(0,   pww, o_ww);
    addr23_kernel<<<128, 512, 0, s2>>>(128, pww, o_ww);

    sweep2_kernel<<<512, 256, 0, 0 >>>(0,   mem, o_mem, o_ww);
    sweep2_kernel<<<512, 256, 0, s2>>>(128, mem, o_mem, o_ww);

    // Join everything back onto main stream
    cudaEventRecord(evJ2, s2);
    cudaStreamWaitEvent(0, evJ2, 0);
    cudaStreamWaitEvent(0, evJA, 0);
    cudaStreamWaitEvent(0, evJB, 0);
}

// round 17
// speedup vs baseline: 1.3326x; 1.0419x over previous
#include <cuda_runtime.h>
#include <math.h>

// Problem constants
constexpr int B_  = 256;
constexpr int N_  = 2048;
constexpr int M_  = 64;
constexpr int C_  = 512;
constexpr int PR_ = 70;   // M + 3 + SHIFT
constexpr int PW_ = 198;  // PR + 2M
constexpr float EPSF = 1e-8f;

// Output layout (floats): ntm_out, memory, read_out, new_read_w, new_write_w
constexpr size_t OUT_MEM = 65536;
constexpr size_t OUT_RO  = 33619968;
constexpr size_t OUT_RW  = 33685504;
constexpr size_t OUT_WW  = 35782656;

// ---------------- device scratch ----------------
__device__ float g_ctrl[B_*C_];
__device__ float g_rp  [4*B_*PR_];
__device__ float g_wp  [4*B_*PW_];
__device__ float g_dot [5*(size_t)B_*N_];
__device__ float g_norm[(size_t)B_*N_];
__device__ float g_base[6*(size_t)B_*N_];   // base dots: Da,Db,S1,S2,T0,T1
__device__ float g_ropart[8*B_*256];

__device__ __forceinline__ float softplusf(float x){ return x > 20.f ? x : log1pf(expf(x)); }
__device__ __forceinline__ float sigmoidf (float x){ return 1.f/(1.f+expf(-x)); }

// ---------------- GEMM body (proven): tile 32x64, K-step 32, 256 threads ----------------
__device__ __forceinline__ void gemm_body(
    const float* __restrict__ A0, int ca,
    const float* __restrict__ A1, int cb,
    const float* __restrict__ W, const float* __restrict__ bias,
    float* __restrict__ out, int Nc)
{
    int col0 = blockIdx.x * 64;
    if (col0 >= Nc) return;
    int row0 = blockIdx.y * 32;
    int K = ca + cb;

    __shared__ float As[32][33];
    __shared__ float Ws[32][64];
    int tid = threadIdx.x;
    int tx = tid & 15, ty = tid >> 4;
    float acc[2][4] = {};

    for (int k0 = 0; k0 < K; k0 += 32) {
        {
            int m  = tid >> 3;
            int kk = (tid & 7) * 4;
            int r = row0 + m, c = k0 + kk;
            float4 v;
            if (c < ca) v = *(const float4*)(A0 + (size_t)r*ca + c);
            else        v = *(const float4*)(A1 + (size_t)r*cb + (c - ca));
            As[m][kk] = v.x; As[m][kk+1] = v.y; As[m][kk+2] = v.z; As[m][kk+3] = v.w;
        }
        {
            int kk = tid >> 3;
            int n0 = (tid & 7) * 8;
            const float* wrow = W + (size_t)(k0 + kk)*Nc + col0 + n0;
            #pragma unroll
            for (int j = 0; j < 8; j++) {
                int gn = col0 + n0 + j;
                Ws[kk][n0 + j] = (gn < Nc) ? wrow[j] : 0.f;
            }
        }
        __syncthreads();
        #pragma unroll
        for (int kk = 0; kk < 32; kk++) {
            float a0 = As[ty*2 + 0][kk];
            float a1 = As[ty*2 + 1][kk];
            float4 w4 = *(const float4*)&Ws[kk][tx*4];
            acc[0][0] += a0*w4.x; acc[0][1] += a0*w4.y; acc[0][2] += a0*w4.z; acc[0][3] += a0*w4.w;
            acc[1][0] += a1*w4.x; acc[1][1] += a1*w4.y; acc[1][2] += a1*w4.z; acc[1][3] += a1*w4.w;
        }
        __syncthreads();
    }
    #pragma unroll
    for (int i = 0; i < 2; i++) {
        int gm = row0 + ty*2 + i;
        #pragma unroll
        for (int j = 0; j < 4; j++) {
            int gn = col0 + tx*4 + j;
            if (gn < Nc) out[(size_t)gm*Nc + gn] = acc[i][j] + bias[gn];
        }
    }
}

__global__ void gemm_cat_kernel(const float* __restrict__ A0, int ca,
                                const float* __restrict__ A1, int cb,
                                const float* __restrict__ W, const float* __restrict__ bias,
                                float* __restrict__ out, int Nc)
{
    gemm_body(A0, ca, A1, cb, W, bias, out, Nc);
}

__global__ void gemm_heads_kernel(const float* __restrict__ ctrl,
                                  const float* __restrict__ readW, const float* __restrict__ readb,
                                  float* __restrict__ rp,
                                  const float* __restrict__ writeW, const float* __restrict__ writeb,
                                  float* __restrict__ wp)
{
    int h = blockIdx.z;
    const float *W, *bias; float* out; int Nc;
    if (h < 4) {
        W = readW + (size_t)h*C_*PR_; bias = readb + h*PR_;
        out = rp + (size_t)h*B_*PR_;  Nc = PR_;
    } else {
        int g = h - 4;
        W = writeW + (size_t)g*C_*PW_; bias = writeb + g*PW_;
        out = wp + (size_t)g*B_*PW_;   Nc = PW_;
    }
    gemm_body(ctrl, C_, nullptr, 0, W, bias, out, Nc);
}

// ---------------- Output GEMM half (rows rb0..rb0+127) with fused ro-sum ----------------
__global__ void __launch_bounds__(256) gemm_out_kernel(
    int rb0,
    const float* __restrict__ ctrl, const float* __restrict__ part,
    const float* __restrict__ W, const float* __restrict__ bias,
    float* __restrict__ out, float* __restrict__ o_ro)
{
    __shared__ float As[32][33];
    __shared__ float Ws[32][64];
    constexpr int Nc = 256;
    int tid = threadIdx.x;
    int cx = blockIdx.x;
    int col0 = cx * 64;
    int row0 = rb0 + blockIdx.y * 32;
    int tx = tid & 15, ty = tid >> 4;
    float acc[2][4] = {};

    for (int k0 = 0; k0 < 768; k0 += 32) {
        {
            int m  = tid >> 3;
            int kk = (tid & 7) * 4;
            int r = row0 + m, c = k0 + kk;
            float4 v;
            if (c < 512) {
                v = *(const float4*)(ctrl + (size_t)r*512 + c);
            } else {
                int cc = c - 512;
                const float* p = part + (size_t)r*256 + cc;
                v = *(const float4*)p;
                #pragma unroll
                for (int q = 1; q < 8; q++) {
                    float4 vq = *(const float4*)(p + (size_t)q*B_*256);
                    v.x += vq.x; v.y += vq.y; v.z += vq.z; v.w += vq.w;
                }
                if (cx == 0)
                    *(float4*)(o_ro + (size_t)r*256 + cc) = v;
            }
            As[m][kk] = v.x; As[m][kk+1] = v.y; As[m][kk+2] = v.z; As[m][kk+3] = v.w;
        }
        {
            int kk = tid >> 3;
            int n0 = (tid & 7) * 8;
            const float* wrow = W + (size_t)(k0 + kk)*Nc + col0 + n0;
            #pragma unroll
            for (int j = 0; j < 8; j++)
                Ws[kk][n0 + j] = wrow[j];
        }
        __syncthreads();
        #pragma unroll
        for (int kk = 0; kk < 32; kk++) {
            float a0 = As[ty*2 + 0][kk];
            float a1 = As[ty*2 + 1][kk];
            float4 w4 = *(const float4*)&Ws[kk][tx*4];
            acc[0][0] += a0*w4.x; acc[0][1] += a0*w4.y; acc[0][2] += a0*w4.z; acc[0][3] += a0*w4.w;
            acc[1][0] += a1*w4.x; acc[1][1] += a1*w4.y; acc[1][2] += a1*w4.z; acc[1][3] += a1*w4.w;
        }
        __syncthreads();
    }
    #pragma unroll
    for (int i = 0; i < 2; i++) {
        int gm = row0 + ty*2 + i;
        #pragma unroll
        for (int j = 0; j < 4; j++) {
            int gn = col0 + tx*4 + j;
            out[(size_t)gm*Nc + gn] = acc[i][j] + bias[gn];
        }
    }
}

// ---------------- Pass A (half): thread-per-row, 8 smem constant vectors ----------------
__global__ void __launch_bounds__(256) passA_kernel(const float* __restrict__ mem, int b0)
{
    int bc = blockIdx.x; int b = b0 + (bc >> 3); int nb = (bc & 7) << 8;
    int tid = threadIdx.x;

    // constants: [0..4]=5 dot keys (4 read + wkey0); [5]=k1 [6]=e0 [7]=a0
    __shared__ float cst[8][64];
    for (int i = tid; i < 5*64; i += 256) {
        int h = i >> 6, m = i & 63;
        cst[h][m] = (h < 4) ? g_rp[((size_t)h*B_ + b)*PR_ + m]
                            : g_wp[(size_t)b*PW_ + m];
    }
    if (tid < 64) {
        const float* wp0 = g_wp + (size_t)b*PW_;
        const float* wp1 = g_wp + ((size_t)B_ + b)*PW_;
        cst[5][tid] = wp1[tid];
        cst[6][tid] = sigmoidf(wp0[70 + tid]);
        cst[7][tid] = tanhf(wp0[134 + tid]);
    }
    __syncthreads();

    size_t ix = (size_t)b*N_ + nb + tid;
    const float4* rp4 = (const float4*)(mem + ix*M_);

    float acc[12] = {};
    #pragma unroll
    for (int mb = 0; mb < 16; mb++) {
        float4 d = rp4[mb];
        float4 c[8];
        #pragma unroll
        for (int ci = 0; ci < 8; ci++)
            c[ci] = *(const float4*)&cst[ci][mb*4];
        float vv[4] = {d.x, d.y, d.z, d.w};
        #pragma unroll
        for (int j = 0; j < 4; j++) {
            float v  = vv[j];
            float e0 = ((const float*)&c[6])[j];
            float a0 = ((const float*)&c[7])[j];
            float k1 = ((const float*)&c[5])[j];
            float ve0 = v*e0;
            acc[0]  += v*v;
            acc[1]  += v * ((const float*)&c[0])[j];
            acc[2]  += v * ((const float*)&c[1])[j];
            acc[3]  += v * ((const float*)&c[2])[j];
            acc[4]  += v * ((const float*)&c[3])[j];
            acc[5]  += v * ((const float*)&c[4])[j];
            acc[6]  += v * k1;        // Da
            acc[7]  += ve0 * k1;      // Db
            acc[8]  += v * ve0;       // S1
            acc[9]  += ve0 * ve0;     // S2
            acc[10] += v * a0;        // T0
            acc[11] += ve0 * a0;      // T1
        }
    }

    const size_t P = (size_t)B_*N_;
    g_norm[ix] = sqrtf(acc[0]);
    #pragma unroll
    for (int h = 0; h < 5; h++) g_dot[(size_t)h*P + ix] = acc[1+h];
    #pragma unroll
    for (int r = 0; r < 6; r++) g_base[(size_t)r*P + ix] = acc[6+r];
}

// ---------------- block reduction helpers (512 threads) ----------------
__device__ __forceinline__ float block_reduce_sum512(float v, float* sbuf)
{
    int tid = threadIdx.x;
    #pragma unroll
    for (int o = 16; o > 0; o >>= 1) v += __shfl_xor_sync(0xffffffffu, v, o);
    if ((tid & 31) == 0) sbuf[tid >> 5] = v;
    __syncthreads();
    if (tid < 32) {
        float x = (tid < 16) ? sbuf[tid] : 0.f;
        #pragma unroll
        for (int o = 8; o > 0; o >>= 1) x += __shfl_xor_sync(0xffffffffu, x, o);
        if (tid == 0) sbuf[0] = x;
    }
    __syncthreads();
    float r = sbuf[0];
    __syncthreads();
    return r;
}

__device__ __forceinline__ float block_reduce_max512(float v, float* sbuf)
{
    int tid = threadIdx.x;
    #pragma unroll
    for (int o = 16; o > 0; o >>= 1) v = fmaxf(v, __shfl_xor_sync(0xffffffffu, v, o));
    if ((tid & 31) == 0) sbuf[tid >> 5] = v;
    __syncthreads();
    if (tid < 32) {
        float x = (tid < 16) ? sbuf[tid] : -3.4e38f;
        #pragma unroll
        for (int o = 8; o > 0; o >>= 1) x = fmaxf(x, __shfl_xor_sync(0xffffffffu, x, o));
        if (tid == 0) sbuf[0] = x;
    }
    __syncthreads();
    float r = sbuf[0];
    __syncthreads();
    return r;
}

// ---------------- addressing tail (512 threads, 4 items/thread) ----------------
__device__ __forceinline__ void address_tail(
    float* x, float g, float s0, float s1, float s2, float gamma,
    const float* __restrict__ wpb, float* __restrict__ woutb,
    float* wg, float* rbuf)
{
    int tid = threadIdx.x;
    float mx = fmaxf(fmaxf(x[0], x[1]), fmaxf(x[2], x[3]));
    float bmax = block_reduce_max512(mx, rbuf);
    float lsum = 0.f;
    #pragma unroll
    for (int i = 0; i < 4; i++) {
        float e = __expf(x[i] - bmax);
        wg[tid + i*512] = e;
        lsum += e;
    }
    float bsum = block_reduce_sum512(lsum, rbuf);
    float inv = 1.f / bsum;
    #pragma unroll
    for (int i = 0; i < 4; i++) {
        int n = tid + i*512;
        wg[n] = g * (wg[n]*inv) + (1.f-g) * wpb[n];
    }
    __syncthreads();
    float wpow[4];
    lsum = 0.f;
    #pragma unroll
    for (int i = 0; i < 4; i++) {
        int n = tid + i*512;
        float ws = s0*wg[(n+1)&(N_-1)] + s1*wg[n] + s2*wg[(n-1)&(N_-1)];
        float t = __powf(ws + EPSF, gamma);
        wpow[i] = t;
        lsum += t;
    }
    float psum = block_reduce_sum512(lsum, rbuf);
    float ip = 1.f / psum;
    #pragma unroll
    for (int i = 0; i < 4; i++) {
        float wv = wpow[i]*ip;
        woutb[tid + i*512] = wv;
        x[i] = wv;
    }
}

__device__ __forceinline__ void head_scalars(const float* __restrict__ p, float ksum, float* sc)
{
    sc[0] = sqrtf(ksum);
    sc[1] = softplusf(p[64]);
    sc[2] = sigmoidf(p[65]);
    float a0 = p[66], a1 = p[67], a2 = p[68];
    float mx = fmaxf(a0, fmaxf(a1, a2));
    float e0 = expf(a0-mx), e1 = expf(a1-mx), e2 = expf(a2-mx);
    float es = e0 + e1 + e2;
    sc[3] = e0/es; sc[4] = e1/es; sc[5] = e2/es;
    sc[6] = 1.f + softplusf(p[69]);
}

__device__ __forceinline__ void poly_x(
    float* x, const float* wdone, size_t base,
    float CC, float UU, float knorm, float beta)
{
    int tid = threadIdx.x;
    const size_t P = (size_t)B_*N_;
    const float* nrmp = g_norm + base;
    #pragma unroll
    for (int i = 0; i < 4; i++) {
        int n = tid + i*512;
        float w  = wdone[i];
        float Da = g_base[0*P + base + n];
        float Db = g_base[1*P + base + n];
        float S1 = g_base[2*P + base + n];
        float S2 = g_base[3*P + base + n];
        float T0 = g_base[4*P + base + n];
        float T1 = g_base[5*P + base + n];
        float nr = nrmp[n];
        float S0 = nr*nr;
        float dotv = Da - w*Db + w*CC;
        float w2 = w*w;
        float nsq = S0 - 2.f*w*S1 + w2*S2 + 2.f*w*T0 - 2.f*w2*T1 + w2*UU;
        float nn = sqrtf(fmaxf(nsq, 0.f));
        x[i] = beta * (dotv / (nn*knorm + EPSF));
    }
}

// ---------------- fused addressing (half): write heads 0&1 (y=0) + 4 read heads ----------------
__global__ void __launch_bounds__(512) address5_kernel(
    int b0,
    const float* __restrict__ prw,
    const float* __restrict__ pww,
    float* __restrict__ o_rw,
    float* __restrict__ o_ww)
{
    __shared__ float wg[2048];
    __shared__ float rbuf[32];
    __shared__ float sc[16];
    int b = b0 + blockIdx.x, hy = blockIdx.y, tid = threadIdx.x;
    size_t base = (size_t)b*N_;
    const size_t P = (size_t)B_*N_;

    if (hy != 0) {
        int h = hy - 1;
        const float* p = g_rp + ((size_t)h*B_ + b)*PR_;
        float kv = 0.f;
        if (tid < 64) { float xx = p[tid]; kv = xx*xx; }
        float ksum = block_reduce_sum512(kv, rbuf);
        if (tid == 0) head_scalars(p, ksum, sc);
        __syncthreads();
        float knorm = sc[0], beta = sc[1], g = sc[2];
        float s0 = sc[3], s1 = sc[4], s2 = sc[5], gamma = sc[6];

        const float* dotb = g_dot + (size_t)h*P + base;
        const float* nrmb = g_norm + base;
        float x[4];
        #pragma unroll
        for (int i = 0; i < 4; i++) {
            int n = tid + i*512;
            x[i] = beta * (dotb[n] / (nrmb[n]*knorm + EPSF));
        }
        address_tail(x, g, s0, s1, s2, gamma,
                     prw + (size_t)h*P + base, o_rw + (size_t)h*P + base, wg, rbuf);
    } else {
        const float* p0 = g_wp + (size_t)b*PW_;
        const float* p1 = g_wp + ((size_t)1*B_ + b)*PW_;
        float kv0 = 0.f, kv1 = 0.f, c1 = 0.f, c2 = 0.f;
        if (tid < 64) {
            float k0 = p0[tid], k1 = p1[tid];
            float a0 = tanhf(p0[134 + tid]);
            kv0 = k0*k0; kv1 = k1*k1; c1 = a0*k1; c2 = a0*a0;
        }
        float ks0 = block_reduce_sum512(kv0, rbuf);
        float ks1 = block_reduce_sum512(kv1, rbuf);
        float Cc  = block_reduce_sum512(c1, rbuf);
        float U   = block_reduce_sum512(c2, rbuf);
        if (tid == 0) {
            head_scalars(p0, ks0, sc);
            head_scalars(p1, ks1, sc + 7);
            sc[14] = Cc; sc[15] = U;
        }
        __syncthreads();

        float knorm = sc[0], beta = sc[1], g = sc[2];
        float s0 = sc[3], s1 = sc[4], s2 = sc[5], gamma = sc[6];
        const float* dotb = g_dot + 4*P + base;
        const float* nrmb = g_norm + base;
        float x[4];
        #pragma unroll
        for (int i = 0; i < 4; i++) {
            int n = tid + i*512;
            x[i] = beta * (dotb[n] / (nrmb[n]*knorm + EPSF));
        }
        address_tail(x, g, s0, s1, s2, gamma, pww + base, o_ww + base, wg, rbuf);
        __syncthreads();
        float y[4];
        poly_x(y, x, base, sc[14], sc[15], sc[7], sc[8]);
        address_tail(y, sc[9], sc[10], sc[11], sc[12], sc[13],
                     pww + P + base, o_ww + P + base, wg, rbuf);
    }
}

// ---------------- fused write heads 2 & 3 (half) ----------------
__global__ void __launch_bounds__(512) addr23_kernel(
    int b0,
    const float* __restrict__ pww,
    float* __restrict__ o_ww)
{
    __shared__ float wg[2048];
    __shared__ float rbuf[32];
    __shared__ float sc[16];
    int b = b0 + blockIdx.x, tid = threadIdx.x;
    size_t base = (size_t)b*N_;
    const size_t P = (size_t)B_*N_;

    const float* p2 = g_wp + ((size_t)2*B_ + b)*PW_;
    const float* p3 = g_wp + ((size_t)3*B_ + b)*PW_;
    float kv2 = 0.f, kv3 = 0.f, c1 = 0.f, c2 = 0.f;
    if (tid < 64) {
        float k2 = p2[tid], k3 = p3[tid];
        float a2 = tanhf(p2[134 + tid]);
        kv2 = k2*k2; kv3 = k3*k3; c1 = a2*k3; c2 = a2*a2;
    }
    float ks2 = block_reduce_sum512(kv2, rbuf);
    float ks3 = block_reduce_sum512(kv3, rbuf);
    float Cc  = block_reduce_sum512(c1, rbuf);
    float U   = block_reduce_sum512(c2, rbuf);
    if (tid == 0) {
        head_scalars(p2, ks2, sc);
        head_scalars(p3, ks3, sc + 7);
        sc[14] = Cc; sc[15] = U;
    }
    __syncthreads();

    float knorm = sc[0], beta = sc[1], g = sc[2];
    float s0 = sc[3], s1 = sc[4], s2 = sc[5], gamma = sc[6];
    const float* dotb = g_dot + 4*P + base;
    const float* nrmb = g_norm + base;
    float x[4];
    #pragma unroll
    for (int i = 0; i < 4; i++) {
        int n = tid + i*512;
        x[i] = beta * (dotb[n] / (nrmb[n]*knorm + EPSF));
    }
    address_tail(x, g, s0, s1, s2, gamma, pww + 2*P + base, o_ww + 2*P + base, wg, rbuf);
    __syncthreads();
    float y[4];
    poly_x(y, x, base, sc[14], sc[15], sc[7], sc[8]);
    address_tail(y, sc[9], sc[10], sc[11], sc[12], sc[13],
                 pww + 3*P + base, o_ww + 3*P + base, wg, rbuf);
}

// ---------------- Sweep 1 (half, two-phase thread-per-row): stats + reads einsum --------------
__global__ void __launch_bounds__(256) sweep1_kernel(
    int b0,
    const float* __restrict__ mem_in,
    const float* __restrict__ wr,
    const float* __restrict__ wwp,
    float* __restrict__ ro_part)
{
    int bc = blockIdx.x; int b = b0 + (bc >> 3); int nb = (bc & 7) << 8;
    int tid = threadIdx.x, wid = tid >> 5, lane = tid & 31;
    const size_t P = (size_t)B_*N_;

    // constants: [0]=e0 [1]=a0 [2]=e1 [3]=a1 [4]=k2 [5]=k3 [6]=e2 [7]=a2
    __shared__ float cst[8][64];
    __shared__ float ws4[256][4];
    __shared__ float2 sred[8][4][32];
    if (tid < 64) {
        const float* p0 = g_wp + (size_t)b*PW_;
        const float* p1 = g_wp + ((size_t)1*B_ + b)*PW_;
        const float* p2 = g_wp + ((size_t)2*B_ + b)*PW_;
        const float* p3 = g_wp + ((size_t)3*B_ + b)*PW_;
        cst[0][tid] = sigmoidf(p0[70 + tid]);
        cst[1][tid] = tanhf(p0[134 + tid]);
        cst[2][tid] = sigmoidf(p1[70 + tid]);
        cst[3][tid] = tanhf(p1[134 + tid]);
        cst[4][tid] = p2[tid];
        cst[5][tid] = p3[tid];
        cst[6][tid] = sigmoidf(p2[70 + tid]);
        cst[7][tid] = tanhf(p2[134 + tid]);
    }
    size_t ix = (size_t)b*N_ + nb + tid;
    #pragma unroll
    for (int h = 0; h < 4; h++) ws4[tid][h] = wr[(size_t)h*P + ix];
    __syncthreads();

    // phase 1: per-row stats
    float w0 = wwp[ix], w1 = wwp[P + ix];
    const float4* rp4 = (const float4*)(mem_in + ix*M_);
    float acc[8] = {};
    #pragma unroll
    for (int mb = 0; mb < 16; mb++) {
        float4 d = rp4[mb];
        float4 c[8];
        #pragma unroll
        for (int ci = 0; ci < 8; ci++)
            c[ci] = *(const float4*)&cst[ci][mb*4];
        float vv[4] = {d.x, d.y, d.z, d.w};
        #pragma unroll
        for (int j = 0; j < 4; j++) {
            float v  = vv[j];
            float e0 = ((const float*)&c[0])[j], a0 = ((const float*)&c[1])[j];
            float e1 = ((const float*)&c[2])[j], a1 = ((const float*)&c[3])[j];
            float k2 = ((const float*)&c[4])[j], k3 = ((const float*)&c[5])[j];
            float e2 = ((const float*)&c[6])[j], a2 = ((const float*)&c[7])[j];
            float m1 = v*(1.f - w0*e0) + w0*a0;
            float m2 = m1*(1.f - w1*e1) + w1*a1;
            float m2e2 = m2*e2;
            acc[0] += m2 * k2;        // dot2
            acc[1] += m2 * m2;        // norm2^2
            acc[2] += m2 * k3;        // Da
            acc[3] += m2e2 * k3;      // Db
            acc[4] += m2 * m2e2;      // S1
            acc[5] += m2e2 * m2e2;    // S2
            acc[6] += m2 * a2;        // T0
            acc[7] += m2e2 * a2;      // T1
        }
    }
    g_dot[4*P + ix] = acc[0];
    g_norm[ix] = sqrtf(acc[1]);
    #pragma unroll
    for (int r = 0; r < 6; r++) g_base[(size_t)r*P + ix] = acc[2+r];

    // phase 2: reads einsum (lane-per-m, L1/L2-hot re-read)
    float2 racc[4] = {{0,0},{0,0},{0,0},{0,0}};
    size_t rowbase = (size_t)b*N_ + nb + wid*32;
    #pragma unroll 4
    for (int r = 0; r < 32; r++) {
        float2 v2 = *(const float2*)(mem_in + (rowbase + r)*M_ + 2*lane);
        float4 w4 = *(const float4*)&ws4[wid*32 + r][0];
        racc[0].x += w4.x*v2.x; racc[0].y += w4.x*v2.y;
        racc[1].x += w4.y*v2.x; racc[1].y += w4.y*v2.y;
        racc[2].x += w4.z*v2.x; racc[2].y += w4.z*v2.y;
        racc[3].x += w4.w*v2.x; racc[3].y += w4.w*v2.y;
    }
    #pragma unroll
    for (int h = 0; h < 4; h++) sred[wid][h][lane] = racc[h];
    __syncthreads();
    int h = tid >> 6, m = tid & 63;
    int l = m >> 1, c = m & 1;
    float s = 0.f;
    #pragma unroll
    for (int w = 0; w < 8; w++) {
        float2 t = sred[w][h][l];
        s += c ? t.y : t.x;
    }
    ro_part[(size_t)(bc & 7)*B_*256 + (size_t)b*256 + h*64 + m] = s;
}

// ---------------- Sweep 2 (half): all 4 head updates, half-warp float4 ----------------
__global__ void __launch_bounds__(256) sweep2_kernel(
    int b0,
    const float* __restrict__ mem_in, float* __restrict__ mem_out,
    const float* __restrict__ wwp)
{
    int bc = blockIdx.x; int b = b0 + (bc >> 2); int nb = (bc & 3) << 9;
    int tid = threadIdx.x, wid = tid >> 5, lane = tid & 31;
    int hw = lane >> 4, l16 = lane & 15;

    float e[4][4], a[4][4];
    #pragma unroll
    for (int h = 0; h < 4; h++) {
        const float* ph = g_wp + ((size_t)h*B_ + b)*PW_;
        #pragma unroll
        for (int j = 0; j < 4; j++) {
            int m = l16*4 + j;
            e[h][j] = sigmoidf(ph[70 + m]);
            a[h][j] = tanhf(ph[134 + m]);
        }
    }

    const size_t P = (size_t)B_*N_;
    for (int it = 0; it < 32; it += 4) {
        int r0 = it*16 + wid*2 + hw;
        size_t ix[4];
        float4 v[4];
        #pragma unroll
        for (int q = 0; q < 4; q++) {
            ix[q] = (size_t)b*N_ + nb + r0 + q*16;
            v[q] = *(const float4*)(mem_in + ix[q]*M_ + l16*4);
        }
        float w[4][4];
        #pragma unroll
        for (int q = 0; q < 4; q++)
            #pragma unroll
            for (int h = 0; h < 4; h++)
                w[q][h] = wwp[(size_t)h*P + ix[q]];

        #pragma unroll
        for (int q = 0; q < 4; q++) {
            float vv[4] = {v[q].x, v[q].y, v[q].z, v[q].w};
            #pragma unroll
            for (int j = 0; j < 4; j++) {
                float m = vv[j];
                #pragma unroll
                for (int h = 0; h < 4; h++)
                    m = m*(1.f - w[q][h]*e[h][j]) + w[q][h]*a[h][j];
                vv[j] = m;
            }
            *(float4*)(mem_out + ix[q]*M_ + l16*4) = make_float4(vv[0], vv[1], vv[2], vv[3]);
        }
    }
}

// ---------------- host launcher ----------------
extern "C" void kernel_launch(void* const* d_in, const int* in_sizes, int n_in,
                              void* d_out, int out_size)
{
    const float* ext    = (const float*)d_in[0];
    const float* pread  = (const float*)d_in[1];
    const float* prw    = (const float*)d_in[2];
    const float* pww    = (const float*)d_in[3];
    const float* mem    = (const float*)d_in[4];
    const float* ctrlW  = (const float*)d_in[5];
    const float* ctrlb  = (const float*)d_in[6];
    const float* readW  = (const float*)d_in[7];
    const float* readb  = (const float*)d_in[8];
    const float* writeW = (const float*)d_in[9];
    const float* writeb = (const float*)d_in[10];
    const float* outW   = (const float*)d_in[11];
    const float* outb   = (const float*)d_in[12];
    float* out = (float*)d_out;

    float *ctrl, *rp, *wp, *ropart;
    cudaGetSymbolAddress((void**)&ctrl,   g_ctrl);
    cudaGetSymbolAddress((void**)&rp,     g_rp);
    cudaGetSymbolAddress((void**)&wp,     g_wp);
    cudaGetSymbolAddress((void**)&ropart, g_ropart);

    float* o_mem = out + OUT_MEM;
    float* o_ro  = out + OUT_RO;
    float* o_rw  = out + OUT_RW;
    float* o_ww  = out + OUT_WW;

    // Streams/events (created once on the uncaptured correctness call).
    static cudaStream_t s2 = nullptr, s3 = nullptr, s4 = nullptr;
    static cudaEvent_t evFork = nullptr, evA = nullptr, evB = nullptr;
    static cudaEvent_t evJA = nullptr, evJB = nullptr, evJ2 = nullptr;
    if (s2 == nullptr) {
        cudaStreamCreateWithFlags(&s2, cudaStreamNonBlocking);
        cudaStreamCreateWithFlags(&s3, cudaStreamNonBlocking);
        cudaStreamCreateWithFlags(&s4, cudaStreamNonBlocking);
        cudaEventCreateWithFlags(&evFork, cudaEventDisableTiming);
        cudaEventCreateWithFlags(&evA, cudaEventDisableTiming);
        cudaEventCreateWithFlags(&evB, cudaEventDisableTiming);
        cudaEventCreateWithFlags(&evJA, cudaEventDisableTiming);
        cudaEventCreateWithFlags(&evJB, cudaEventDisableTiming);
        cudaEventCreateWithFlags(&evJ2, cudaEventDisableTiming);
    }

    // Shared prologue on main stream
    gemm_cat_kernel<<<dim3(8, 8), 256>>>(ext, 256, pread, 256, ctrlW, ctrlb, ctrl, 512);
    gemm_heads_kernel<<<dim3(4, 8, 8), 256>>>(ctrl, readW, readb, rp, writeW, writeb, wp);

    // Fork batch-half 1 onto s2
    cudaEventRecord(evFork, 0);
    cudaStreamWaitEvent(s2, evFork, 0);

    // Half 0 (b 0..127) on main stream; half 1 (b 128..255) on s2 — interleaved launches
    passA_kernel<<<1024, 256, 0, 0 >>>(mem, 0);
    passA_kernel<<<1024, 256, 0, s2>>>(mem, 128);

    address5_kernel<<<dim3(128, 5), 512, 0, 0 >>>(0,   prw, pww, o_rw, o_ww);
    address5_kernel<<<dim3(128, 5), 512, 0, s2>>>(128, prw, pww, o_rw, o_ww);

    sweep1_kernel<<<1024, 256, 0, 0 >>>(0,   mem, o_rw, o_ww, ropart);
    sweep1_kernel<<<1024, 256, 0, s2>>>(128, mem, o_rw, o_ww, ropart);

    // Out-GEMM halves fork off each half's sweep1 (rows == b)
    cudaEventRecord(evA, 0);
    cudaStreamWaitEvent(s3, evA, 0);
    gemm_out_kernel<<<dim3(4, 4), 256, 0, s3>>>(0,   ctrl, ropart, outW, outb, out, o_ro);
    cudaEventRecord(evJA, s3);

    cudaEventRecord(evB, s2);
    cudaStreamWaitEvent(s4, evB, 0);
    gemm_out_kernel<<<dim3(4, 4), 256, 0, s4>>>(128, ctrl, ropart, outW, outb, out, o_ro);
    cudaEventRecord(evJB, s4);

    // Write heads 2&3 + final sweep per half
    addr23_kernel<<<128, 512, 0, 0 >>>(0,   pww, o_ww);
    addr23_kernel<<<128, 512, 0, s2>>>(128, pww, o_ww);

    sweep2_kernel<<<512, 256, 0, 0 >>>(0,   mem, o_mem, o_ww);
    sweep2_kernel<<<512, 256, 0, s2>>>(128, mem, o_mem, o_ww);

    // Join everything back onto main stream
    cudaEventRecord(evJ2, s2);
    cudaStreamWaitEvent(0, evJ2, 0);
    cudaStreamWaitEvent(0, evJA, 0);
    cudaStreamWaitEvent(0, evJB, 0);
}